// round 10
// baseline (speedup 1.0000x reference)
#include <cuda_runtime.h>
#include <cuda_bf16.h>
#include <cuda_fp16.h>
#include <math.h>
#include <stdint.h>

#define Bb 128
#define Tt 30
#define Vv 10000
#define Hh 512
#define Ff 4096
#define BH (Bb*Hh)
#define TBH (Tt*Bb*Hh)
#define Vpad 10112
#define SZGRU (512*1024)

typedef __nv_bfloat16 bf16;
typedef __nv_bfloat162 bf162;

__device__ float g_h0f[BH], g_h1f[BH], g_u0f[BH], g_u1f[BH];
__device__ float g_Xu0[TBH], g_Xr0[TBH], g_Xc0[TBH];
__device__ float g_ipart[4][BH];

__device__ __align__(16) bf16 g_vgg_h[Bb*Ff], g_vgg_l[Bb*Ff];
__device__ __align__(16) bf16 g_xemb_h[TBH], g_xemb_l[TBH];
__device__ __align__(16) bf16 g_h0h[BH], g_h0l[BH];
__device__ __align__(16) bf16 g_rh0h[BH], g_rh0l[BH];
__device__ __align__(16) bf16 g_c1h[Bb*1024], g_c1l[Bb*1024];
__device__ __align__(16) bf16 g_c2h[2][Bb*1024], g_c2l[2][Bb*1024];
__device__ __align__(16) __half g_X1ah[TBH], g_X1al[TBH];   // fp16 hi/lo X1
__device__ __align__(16) bf16 g_Win_h[Hh*Ff], g_Win_l[Hh*Ff];
__device__ __align__(16) bf16 g_Wgru_h[6*SZGRU], g_Wgru_l[6*SZGRU];
__device__ __align__(16) __half g_WoH[Vpad*Hh];             // fp16 W_out [N,K]

__device__ __forceinline__ uint32_t smem_u32(const void* p) {
    uint32_t a;
    asm("{ .reg .u64 t; cvta.to.shared.u64 t, %1; cvt.u32.u64 %0, t; }" : "=r"(a) : "l"(p));
    return a;
}
__device__ __forceinline__ void cpasync16(uint32_t dst, const void* src) {
    asm volatile("cp.async.cg.shared.global [%0], [%1], 16;" :: "r"(dst), "l"(src) : "memory");
}
#define CP_COMMIT() asm volatile("cp.async.commit_group;" ::: "memory")
#define CP_WAIT1()  asm volatile("cp.async.wait_group 1;" ::: "memory")
#define CP_WAIT0()  asm volatile("cp.async.wait_group 0;" ::: "memory")
#define LDSM4(R, addr) \
    asm volatile("ldmatrix.sync.aligned.m8n8.x4.shared.b16 {%0,%1,%2,%3}, [%4];" \
        : "=r"((R)[0]), "=r"((R)[1]), "=r"((R)[2]), "=r"((R)[3]) : "r"(addr))

__device__ __forceinline__ void mmaop(float* c, const uint32_t* a, const uint32_t* b) {
    asm volatile("mma.sync.aligned.m16n8k16.row.col.f32.bf16.bf16.f32 "
        "{%0,%1,%2,%3}, {%4,%5,%6,%7}, {%8,%9}, {%0,%1,%2,%3};"
        : "+f"(c[0]), "+f"(c[1]), "+f"(c[2]), "+f"(c[3])
        : "r"(a[0]), "r"(a[1]), "r"(a[2]), "r"(a[3]), "r"(b[0]), "r"(b[1]));
}
__device__ __forceinline__ void mmaop_h(float* c, const uint32_t* a, const uint32_t* b) {
    asm volatile("mma.sync.aligned.m16n8k16.row.col.f32.f16.f16.f32 "
        "{%0,%1,%2,%3}, {%4,%5,%6,%7}, {%8,%9}, {%0,%1,%2,%3};"
        : "+f"(c[0]), "+f"(c[1]), "+f"(c[2]), "+f"(c[3])
        : "r"(a[0]), "r"(a[1]), "r"(a[2]), "r"(a[3]), "r"(b[0]), "r"(b[1]));
}
__device__ __forceinline__ float sigmoidf_(float x) { return 1.0f / (1.0f + expf(-x)); }
__device__ __forceinline__ void sp2(bf16* H, bf16* L, int i, float a, float b) {
    bf16 ha = __float2bfloat16(a), hb = __float2bfloat16(b);
    bf162 hv; hv.x = ha; hv.y = hb;
    bf162 lv; lv.x = __float2bfloat16(a - __bfloat162float(ha));
    lv.y = __float2bfloat16(b - __bfloat162float(hb));
    *(bf162*)&H[i] = hv; *(bf162*)&L[i] = lv;
}
__device__ __forceinline__ void sp2h(__half* H, __half* L, int i, float a, float b) {
    __half ha = __float2half_rn(a), hb = __float2half_rn(b);
    __half2 hv; hv.x = ha; hv.y = hb;
    __half2 lv; lv.x = __float2half_rn(a - __half2float(ha));
    lv.y = __float2half_rn(b - __half2float(hb));
    *(__half2*)&H[i] = hv; *(__half2*)&L[i] = lv;
}

// ---- generic split-3 bf16 mma GEMM: D[TM x TN] = A[TM,K] @ B[N,K]^T ----
#define ROWB 80
template<int TM, int TN, typename Epi>
__device__ __forceinline__ void mma_gemm(
    const bf16* __restrict__ Ah, const bf16* __restrict__ Al, int lda, int m0,
    const bf16* __restrict__ Bh, const bf16* __restrict__ Bl, int ldb, int n0,
    int K, Epi epi)
{
    extern __shared__ char smem[];
    constexpr int ASZ = TM * ROWB, BSZ = TN * ROWB, STG = 2*ASZ + 2*BSZ;
    constexpr int WM = TM / 4, WN = TN / 2, FM = WM / 16, NF = WN / 8;
    constexpr int GG = (NF > 4) ? 4 : NF;
    const uint32_t s0 = smem_u32(smem);
    const int tid = threadIdx.x, lane = tid & 31, wid = tid >> 5;
    const int wm = wid >> 1, wn = wid & 1;
    const int lrow = lane & 15, lhalf = lane >> 4;
    float acc[FM][NF][4] = {};

    auto issue = [&](int ch, int st) {
        uint32_t d = s0 + st * STG;
        int k0 = ch * 32;
        #pragma unroll
        for (int v = tid; v < TM * 4; v += 256) {
            int row = v >> 2, c = v & 3;
            cpasync16(d + row*ROWB + c*16,       Ah + (m0+row)*lda + k0 + c*8);
            cpasync16(d + ASZ + row*ROWB + c*16, Al + (m0+row)*lda + k0 + c*8);
        }
        #pragma unroll
        for (int v = tid; v < TN * 4; v += 256) {
            int row = v >> 2, c = v & 3;
            cpasync16(d + 2*ASZ + row*ROWB + c*16,       Bh + (n0+row)*ldb + k0 + c*8);
            cpasync16(d + 2*ASZ + BSZ + row*ROWB + c*16, Bl + (n0+row)*ldb + k0 + c*8);
        }
        CP_COMMIT();
    };

    const int NC = K / 32;
    issue(0, 0);
    for (int ch = 0; ch < NC; ch++) {
        int st = ch & 1;
        if (ch + 1 < NC) { issue(ch + 1, (ch + 1) & 1); CP_WAIT1(); }
        else CP_WAIT0();
        __syncthreads();
        uint32_t d = s0 + st * STG;
        #pragma unroll
        for (int kk = 0; kk < 2; kk++) {
            uint32_t ah[FM][4], al[FM][4];
            #pragma unroll
            for (int f = 0; f < FM; f++) {
                uint32_t a = d + (wm*WM + f*16 + lrow)*ROWB + lhalf*16 + kk*32;
                LDSM4(ah[f], a);
                LDSM4(al[f], a + ASZ);
            }
            #pragma unroll
            for (int gg = 0; gg < NF; gg += GG) {
                uint32_t bh[GG][2], bl[GG][2];
                #pragma unroll
                for (int g2 = 0; g2 < GG; g2 += 2) {
                    int g = gg + g2;
                    uint32_t b = d + 2*ASZ + (wn*WN + g*8 + lrow)*ROWB + lhalf*16 + kk*32;
                    uint32_t t4[4];
                    LDSM4(t4, b);
                    bh[g2][0]=t4[0]; bh[g2][1]=t4[2]; bh[g2+1][0]=t4[1]; bh[g2+1][1]=t4[3];
                    LDSM4(t4, b + BSZ);
                    bl[g2][0]=t4[0]; bl[g2][1]=t4[2]; bl[g2+1][0]=t4[1]; bl[g2+1][1]=t4[3];
                }
                #pragma unroll
                for (int f = 0; f < FM; f++)
                    #pragma unroll
                    for (int g2 = 0; g2 < GG; g2++) {
                        mmaop(acc[f][gg+g2], ah[f], bh[g2]);
                        mmaop(acc[f][gg+g2], ah[f], bl[g2]);
                        mmaop(acc[f][gg+g2], al[f], bh[g2]);
                    }
            }
        }
        __syncthreads();
    }
    #pragma unroll
    for (int f = 0; f < FM; f++)
        #pragma unroll
        for (int g = 0; g < NF; g++) {
            int r = m0 + wm*WM + f*16 + (lane >> 2);
            int c = n0 + wn*WN + g*8 + (lane & 3)*2;
            epi(r,     c, acc[f][g][0], acc[f][g][1]);
            epi(r + 8, c, acc[f][g][2], acc[f][g][3]);
        }
}

// ---- 2-term fp16 GEMM: D = (Ah+Al)[TM,K] @ Bh[N,K]^T ----
template<int TM, int TN, typename Epi>
__device__ __forceinline__ void mma_gemm_h2(
    const __half* __restrict__ Ah, const __half* __restrict__ Al, int lda, int m0,
    const __half* __restrict__ Bh, int ldb, int n0, int K, Epi epi)
{
    extern __shared__ char smem[];
    constexpr int ASZ = TM * ROWB, BSZ = TN * ROWB, STG = 2*ASZ + BSZ;
    constexpr int WM = TM / 4, WN = TN / 2, FM = WM / 16, NF = WN / 8;
    constexpr int GG = (NF > 4) ? 4 : NF;
    const uint32_t s0 = smem_u32(smem);
    const int tid = threadIdx.x, lane = tid & 31, wid = tid >> 5;
    const int wm = wid >> 1, wn = wid & 1;
    const int lrow = lane & 15, lhalf = lane >> 4;
    float acc[FM][NF][4] = {};

    auto issue = [&](int ch, int st) {
        uint32_t d = s0 + st * STG;
        int k0 = ch * 32;
        #pragma unroll
        for (int v = tid; v < TM * 4; v += 256) {
            int row = v >> 2, c = v & 3;
            cpasync16(d + row*ROWB + c*16,       Ah + (m0+row)*lda + k0 + c*8);
            cpasync16(d + ASZ + row*ROWB + c*16, Al + (m0+row)*lda + k0 + c*8);
        }
        #pragma unroll
        for (int v = tid; v < TN * 4; v += 256) {
            int row = v >> 2, c = v & 3;
            cpasync16(d + 2*ASZ + row*ROWB + c*16, Bh + (n0+row)*ldb + k0 + c*8);
        }
        CP_COMMIT();
    };

    const int NC = K / 32;
    issue(0, 0);
    for (int ch = 0; ch < NC; ch++) {
        int st = ch & 1;
        if (ch + 1 < NC) { issue(ch + 1, (ch + 1) & 1); CP_WAIT1(); }
        else CP_WAIT0();
        __syncthreads();
        uint32_t d = s0 + st * STG;
        #pragma unroll
        for (int kk = 0; kk < 2; kk++) {
            uint32_t ah[FM][4], al[FM][4];
            #pragma unroll
            for (int f = 0; f < FM; f++) {
                uint32_t a = d + (wm*WM + f*16 + lrow)*ROWB + lhalf*16 + kk*32;
                LDSM4(ah[f], a);
                LDSM4(al[f], a + ASZ);
            }
            #pragma unroll
            for (int gg = 0; gg < NF; gg += GG) {
                uint32_t bh[GG][2];
                #pragma unroll
                for (int g2 = 0; g2 < GG; g2 += 2) {
                    int g = gg + g2;
                    uint32_t b = d + 2*ASZ + (wn*WN + g*8 + lrow)*ROWB + lhalf*16 + kk*32;
                    uint32_t t4[4];
                    LDSM4(t4, b);
                    bh[g2][0]=t4[0]; bh[g2][1]=t4[2]; bh[g2+1][0]=t4[1]; bh[g2+1][1]=t4[3];
                }
                #pragma unroll
                for (int f = 0; f < FM; f++)
                    #pragma unroll
                    for (int g2 = 0; g2 < GG; g2++) {
                        mmaop_h(acc[f][gg+g2], ah[f], bh[g2]);
                        mmaop_h(acc[f][gg+g2], al[f], bh[g2]);
                    }
            }
        }
        __syncthreads();
    }
    #pragma unroll
    for (int f = 0; f < FM; f++)
        #pragma unroll
        for (int g = 0; g < NF; g++) {
            int r = m0 + wm*WM + f*16 + (lane >> 2);
            int c = n0 + wn*WN + g*8 + (lane & 3)*2;
            epi(r,     c, acc[f][g][0], acc[f][g][1]);
            epi(r + 8, c, acc[f][g][2], acc[f][g][3]);
        }
}
#define SMEM_S  (2 * (2*64*ROWB + 2*32*ROWB))      // 30720 (64x32 3-term)
#define SM66    (2 * (2*64*ROWB + 2*64*ROWB))      // 40960 (64x64 3-term)
#define SMEM_X  (2 * (2*128*ROWB + 2*128*ROWB))    // 81920 (128x128 3-term)
#define SMEM_H  (2 * (2*128*ROWB + 128*ROWB))      // 61440 (128x128 2-term fp16)

// ---- prepack ----
__device__ __forceinline__ void pk_T_body(const float* __restrict__ src,
                                          bf16* __restrict__ dh, bf16* __restrict__ dl,
                                          int K, int N, int Npad, int kb, int nb)
{
    __shared__ float tile[32][33];
    int tx = threadIdx.x & 31, ty = threadIdx.x >> 5;
    for (int i = ty; i < 32; i += 8) {
        int n = nb + tx;
        tile[i][tx] = (n < N) ? src[(kb + i) * N + n] : 0.f;
    }
    __syncthreads();
    for (int i = ty; i < 32; i += 8) {
        int n = nb + i, k = kb + tx;
        if (n < Npad) {
            float x = tile[tx][i];
            bf16 h = __float2bfloat16(x);
            dh[n * K + k] = h;
            dl[n * K + k] = __float2bfloat16(x - __bfloat162float(h));
        }
    }
}
__global__ __launch_bounds__(256) void pk_T(const float* __restrict__ src,
                                            bf16* __restrict__ dh, bf16* __restrict__ dl,
                                            int K, int N, int Npad)
{
    pk_T_body(src, dh, dl, K, N, Npad, blockIdx.y * 32, blockIdx.x * 32);
}
__global__ __launch_bounds__(256) void pk_gru(const float* __restrict__ Wu,
                                              const float* __restrict__ Wr,
                                              const float* __restrict__ Wc,
                                              bf16* __restrict__ Wgh,
                                              bf16* __restrict__ Wgl)
{
    int z = blockIdx.z;
    int gate = (z < 3) ? z : z - 3, layer = z / 3;
    const float* src = ((gate == 0) ? Wu : (gate == 1) ? Wr : Wc) + layer * 1024 * Hh;
    pk_T_body(src, Wgh + z*SZGRU, Wgl + z*SZGRU, 1024, Hh, Hh,
              blockIdx.y * 32, blockIdx.x * 32);
}
__global__ __launch_bounds__(256) void pk_Wo(const float* __restrict__ src)
{
    __shared__ float tile[32][33];
    int kb = blockIdx.y * 32, nb = blockIdx.x * 32;
    int tx = threadIdx.x & 31, ty = threadIdx.x >> 5;
    for (int i = ty; i < 32; i += 8) {
        int n = nb + tx;
        tile[i][tx] = (n < Vv) ? src[(kb + i) * Vv + n] : 0.f;
    }
    __syncthreads();
    for (int i = ty; i < 32; i += 8) {
        int n = nb + i, k = kb + tx;
        g_WoH[n * Hh + k] = __float2half_rn(tile[tx][i]);
    }
}
__global__ __launch_bounds__(256) void pk_vgg(const float* __restrict__ src)
{
    int i = (blockIdx.x * 256 + threadIdx.x) * 2;
    sp2(g_vgg_h, g_vgg_l, i, src[i], src[i + 1]);
}
__global__ __launch_bounds__(256) void k_gather(const float* __restrict__ emb,
                                                const int* __restrict__ tok)
{
    int idx = (blockIdx.x * 256 + threadIdx.x) * 2;
    int r = idx >> 9, e = idx & 511;
    int token = tok[(r & 127) * Tt + (r >> 7)];
    sp2(g_xemb_h, g_xemb_l, idx, emb[token * Hh + e], emb[token * Hh + e + 1]);
}

// ---- init: split-K partials then finalize ----
__global__ __launch_bounds__(256, 1) void k_initp()
{
    int cta = blockIdx.x;
    int ks = cta >> 5, mt = (cta >> 4) & 1, nt = cta & 15;
    int koff = ks * 1024;
    float* out = g_ipart[ks];
    mma_gemm<64,32>(g_vgg_h + koff, g_vgg_l + koff, Ff, mt*64,
                    g_Win_h + koff, g_Win_l + koff, Ff, nt*32, 1024,
        [&](int r, int c, float v0, float v1) {
            out[r*Hh + c] = v0; out[r*Hh + c + 1] = v1;
        });
}
__global__ __launch_bounds__(256) void k_initf(const float* __restrict__ b_in)
{
    int i = blockIdx.x * 256 + threadIdx.x;
    float v = tanhf(g_ipart[0][i] + g_ipart[1][i] + g_ipart[2][i] + g_ipart[3][i]
                    + b_in[i & 511]);
    g_h0f[i] = v; g_h1f[i] = v;
    bf16 h = __float2bfloat16(v);
    bf16 l = __float2bfloat16(v - __bfloat162float(h));
    g_h0h[i] = h; g_h0l[i] = l;
    int ci = (i >> 9) * 1024 + 512 + (i & 511);
    g_c1h[ci] = h; g_c1l[ci] = l;
}

// ---- layer0 x-projections for all t (128x128 tiles) ----
__global__ __launch_bounds__(256, 2) void k_xpre(const float* __restrict__ bu,
                                                 const float* __restrict__ br,
                                                 const float* __restrict__ bc)
{
    int n0 = blockIdx.x * 128, m0 = blockIdx.y * 128, gate = blockIdx.z;
    const float* bi = (gate == 0) ? bu : (gate == 1) ? br : bc;
    float* out = (gate == 0) ? g_Xu0 : (gate == 1) ? g_Xr0 : g_Xc0;
    mma_gemm<128,128>(g_xemb_h, g_xemb_l, Hh, m0,
                      g_Wgru_h + gate*SZGRU, g_Wgru_l + gate*SZGRU, 1024, n0, Hh,
        [&](int r, int c, float v0, float v1) {
            float2 val = make_float2(v0 + bi[c], v1 + bi[c + 1]);
            *(float2*)&out[r*Hh + c] = val;
        });
}

// ---- wave UR: z={0,1}: layer0 u/r @t=w ; z={2,3}: layer1 u/r @t=w-1 (64x64) ----
__global__ __launch_bounds__(256, 1) void k_ur(int w,
                                               const float* __restrict__ bu1,
                                               const float* __restrict__ br1)
{
    int nt = blockIdx.x, mt = blockIdx.y, z = blockIdx.z;
    int n0 = nt * 64;
    if (z < 2) {
        if (w >= Tt) return;
        int gate = z;
        const float* X = (gate ? g_Xr0 : g_Xu0) + w * BH;
        mma_gemm<64,64>(g_h0h, g_h0l, Hh, mt*64,
            g_Wgru_h + gate*SZGRU + 512, g_Wgru_l + gate*SZGRU + 512,
            1024, n0, Hh,
            [&](int r, int c, float v0, float v1) {
                int idx = r*Hh + c;
                float s0 = sigmoidf_(v0 + X[idx]);
                float s1 = sigmoidf_(v1 + X[idx+1]);
                if (gate == 0) { g_u0f[idx] = s0; g_u0f[idx+1] = s1; }
                else sp2(g_rh0h, g_rh0l, idx, s0*g_h0f[idx], s1*g_h0f[idx+1]);
            });
    } else {
        if (w == 0 || w > Tt) return;
        int gate = z - 2, par = (w - 1) & 1;
        const float* bi = gate ? br1 : bu1;
        mma_gemm<64,64>(g_c1h, g_c1l, 1024, mt*64,
            g_Wgru_h + (3+gate)*SZGRU, g_Wgru_l + (3+gate)*SZGRU,
            1024, n0, 1024,
            [&](int r, int c, float v0, float v1) {
                int idx = r*Hh + c;
                float s0 = sigmoidf_(v0 + bi[c]);
                float s1 = sigmoidf_(v1 + bi[c+1]);
                if (gate == 0) { g_u1f[idx] = s0; g_u1f[idx+1] = s1; }
                else sp2(g_c2h[par], g_c2l[par], r*1024 + 512 + c,
                         s0*g_h1f[idx], s1*g_h1f[idx+1]);
            });
    }
}

// ---- wave C (flattened grid, 111 CTAs):
//   q<16: layer0 cand+update @t=w (64x64)
//   16<=q<32: layer1 cand+update @t=w-1 (64x64)
//   q>=32: logits slab for t=w-2 (128x128 fp16 2-term), 79 CTAs ----
__global__ __launch_bounds__(256, 1) void k_c(int w, const float* __restrict__ bc1,
                                              const float* __restrict__ bout,
                                              float* __restrict__ out)
{
    int q = blockIdx.x;
    if (q < 16) {
        if (w >= Tt) return;
        int n0 = (q & 7) * 64, mt = q >> 3;
        int par = w & 1;
        const float* Xc = g_Xc0 + w * BH;
        mma_gemm<64,64>(g_rh0h, g_rh0l, Hh, mt*64,
            g_Wgru_h + 2*SZGRU + 512, g_Wgru_l + 2*SZGRU + 512,
            1024, n0, Hh,
            [&](int r, int c, float v0, float v1) {
                int idx = r*Hh + c;
                float c0 = tanhf(v0 + Xc[idx]), c1 = tanhf(v1 + Xc[idx+1]);
                float u0 = g_u0f[idx], u1 = g_u0f[idx+1];
                float h0 = u0*g_h0f[idx]   + (1.f-u0)*c0;
                float h1 = u1*g_h0f[idx+1] + (1.f-u1)*c1;
                g_h0f[idx] = h0; g_h0f[idx+1] = h1;
                sp2(g_h0h, g_h0l, idx, h0, h1);
                int ci = r*1024 + c;
                sp2(g_c1h, g_c1l, ci, h0, h1);
                sp2(g_c2h[par], g_c2l[par], ci, h0, h1);
            });
    } else if (q < 32) {
        if (w == 0 || w > Tt) return;
        int q2 = q - 16;
        int n0 = (q2 & 7) * 64, mt = q2 >> 3;
        int par = (w - 1) & 1;
        mma_gemm<64,64>(g_c2h[par], g_c2l[par], 1024, mt*64,
            g_Wgru_h + 5*SZGRU, g_Wgru_l + 5*SZGRU, 1024, n0, 1024,
            [&](int r, int c, float v0, float v1) {
                int idx = r*Hh + c;
                float c0 = tanhf(v0 + bc1[c]), c1 = tanhf(v1 + bc1[c+1]);
                float u0 = g_u1f[idx], u1 = g_u1f[idx+1];
                float h0 = u0*g_h1f[idx]   + (1.f-u0)*c0;
                float h1 = u1*g_h1f[idx+1] + (1.f-u1)*c1;
                g_h1f[idx] = h0; g_h1f[idx+1] = h1;
                sp2(g_c1h, g_c1l, r*1024 + 512 + c, h0, h1);
                sp2h(g_X1ah, g_X1al, ((w-1)*Bb + r)*Hh + c, h0, h1);
            });
    } else {
        if (w < 2) return;
        int t = w - 2;
        int n0 = (q - 32) * 128;
        mma_gemm_h2<128,128>(g_X1ah + t*BH, g_X1al + t*BH, Hh, 0,
                             g_WoH, Hh, n0, Hh,
            [&](int r, int c, float v0, float v1) {
                if (c < Vv) {
                    long long base = (long long)(r * Tt + t) * Vv;
                    out[base + c] = v0 + bout[c];
                    if (c + 1 < Vv) out[base + c + 1] = v1 + bout[c + 1];
                }
            });
    }
}

__global__ __launch_bounds__(256) void k_final(float* __restrict__ out)
{
    int i = blockIdx.x * 256 + threadIdx.x;
    out[(long long)Bb * Tt * Vv + i] = (i >> 16) ? g_h1f[i & (BH-1)] : g_h0f[i & (BH-1)];
}

// ---- launch ----
extern "C" void kernel_launch(void* const* d_in, const int* in_sizes, int n_in,
                              void* d_out, int out_size)
{
    const float* vgg   = (const float*)d_in[0];
    const int*   xTok  = (const int*)  d_in[1];
    const float* emb   = (const float*)d_in[2];
    const float* W_in  = (const float*)d_in[3];
    const float* b_in  = (const float*)d_in[4];
    const float* Wu    = (const float*)d_in[5];
    const float* bu    = (const float*)d_in[6];
    const float* Wr    = (const float*)d_in[7];
    const float* br    = (const float*)d_in[8];
    const float* Wc    = (const float*)d_in[9];
    const float* bc    = (const float*)d_in[10];
    const float* W_out = (const float*)d_in[11];
    const float* b_out = (const float*)d_in[12];
    float* out = (float*)d_out;

    cudaFuncSetAttribute(k_xpre, cudaFuncAttributeMaxDynamicSharedMemorySize, SMEM_X);
    cudaFuncSetAttribute(k_c,    cudaFuncAttributeMaxDynamicSharedMemorySize, SMEM_H);

    bf16 *Wgh, *Wgl, *Wih, *Wil;
    cudaGetSymbolAddress((void**)&Wgh, g_Wgru_h);
    cudaGetSymbolAddress((void**)&Wgl, g_Wgru_l);
    cudaGetSymbolAddress((void**)&Wih, g_Win_h);
    cudaGetSymbolAddress((void**)&Wil, g_Win_l);

    pk_vgg<<<(Bb*Ff/2)/256, 256>>>(vgg);
    pk_T<<<dim3(16, 128), 256>>>(W_in, Wih, Wil, Ff, Hh, Hh);
    pk_gru<<<dim3(16, 32, 6), 256>>>(Wu, Wr, Wc, Wgh, Wgl);
    pk_Wo<<<dim3(Vpad/32, 16), 256>>>(W_out);

    k_initp<<<128, 256, SMEM_S>>>();
    k_initf<<<BH/256, 256>>>(b_in);
    k_gather<<<(TBH/2)/256, 256>>>(emb, xTok);
    k_xpre<<<dim3(4, Tt*Bb/128, 3), 256, SMEM_X>>>(bu, br, bc);

    for (int w = 0; w <= Tt; w++) {
        k_ur<<<dim3(8, 2, 4), 256, SM66>>>(w, bu + Hh, br + Hh);
        k_c <<<111, 256, SMEM_H>>>(w, bc + Hh, b_out, out);
    }
    // trailing phase: logits slab for t = Tt-1 only
    k_c<<<111, 256, SMEM_H>>>(Tt + 1, bc + Hh, b_out, out);

    k_final<<<(2*BH)/256, 256>>>(out);
}

// round 11
// speedup vs baseline: 1.0054x; 1.0054x over previous
#include <cuda_runtime.h>
#include <cuda_bf16.h>
#include <cuda_fp16.h>
#include <math.h>
#include <stdint.h>

#define Bb 128
#define Tt 30
#define Vv 10000
#define Hh 512
#define Ff 4096
#define BH (Bb*Hh)
#define TBH (Tt*Bb*Hh)
#define Vpad 10112
#define SZGRU (512*1024)

typedef __nv_bfloat16 bf16;
typedef __nv_bfloat162 bf162;

__device__ float g_h0f[BH], g_h1f[BH], g_u0f[BH], g_u1f[BH];
__device__ float g_Xu0[TBH], g_Xr0[TBH], g_Xc0[TBH];
__device__ float g_ipart[4][BH];

// bf16 operands (init GEMM only)
__device__ __align__(16) bf16 g_vgg_h[Bb*Ff], g_vgg_l[Bb*Ff];
__device__ __align__(16) bf16 g_Win_h[Hh*Ff], g_Win_l[Hh*Ff];

// fp16 hi/lo activations (scan + xpre + logits)
__device__ __align__(16) __half g_xembH[TBH], g_xembL[TBH];
__device__ __align__(16) __half g_h0H[BH], g_h0L[BH];
__device__ __align__(16) __half g_rh0H[BH], g_rh0L[BH];
__device__ __align__(16) __half g_c1H[Bb*1024], g_c1L[Bb*1024];
__device__ __align__(16) __half g_c2H[2][Bb*1024], g_c2L[2][Bb*1024];
__device__ __align__(16) __half g_X1ah[TBH], g_X1al[TBH];

// fp16 single weights
__device__ __align__(16) __half g_WgruH[6*SZGRU];   // [z][N=512, K=1024]
__device__ __align__(16) __half g_WoH[Vpad*Hh];     // [N, K=512]

__device__ __forceinline__ uint32_t smem_u32(const void* p) {
    uint32_t a;
    asm("{ .reg .u64 t; cvta.to.shared.u64 t, %1; cvt.u32.u64 %0, t; }" : "=r"(a) : "l"(p));
    return a;
}
__device__ __forceinline__ void cpasync16(uint32_t dst, const void* src) {
    asm volatile("cp.async.cg.shared.global [%0], [%1], 16;" :: "r"(dst), "l"(src) : "memory");
}
#define CP_COMMIT() asm volatile("cp.async.commit_group;" ::: "memory")
#define CP_WAIT1()  asm volatile("cp.async.wait_group 1;" ::: "memory")
#define CP_WAIT0()  asm volatile("cp.async.wait_group 0;" ::: "memory")
#define LDSM4(R, addr) \
    asm volatile("ldmatrix.sync.aligned.m8n8.x4.shared.b16 {%0,%1,%2,%3}, [%4];" \
        : "=r"((R)[0]), "=r"((R)[1]), "=r"((R)[2]), "=r"((R)[3]) : "r"(addr))

__device__ __forceinline__ void mmaop(float* c, const uint32_t* a, const uint32_t* b) {
    asm volatile("mma.sync.aligned.m16n8k16.row.col.f32.bf16.bf16.f32 "
        "{%0,%1,%2,%3}, {%4,%5,%6,%7}, {%8,%9}, {%0,%1,%2,%3};"
        : "+f"(c[0]), "+f"(c[1]), "+f"(c[2]), "+f"(c[3])
        : "r"(a[0]), "r"(a[1]), "r"(a[2]), "r"(a[3]), "r"(b[0]), "r"(b[1]));
}
__device__ __forceinline__ void mmaop_h(float* c, const uint32_t* a, const uint32_t* b) {
    asm volatile("mma.sync.aligned.m16n8k16.row.col.f32.f16.f16.f32 "
        "{%0,%1,%2,%3}, {%4,%5,%6,%7}, {%8,%9}, {%0,%1,%2,%3};"
        : "+f"(c[0]), "+f"(c[1]), "+f"(c[2]), "+f"(c[3])
        : "r"(a[0]), "r"(a[1]), "r"(a[2]), "r"(a[3]), "r"(b[0]), "r"(b[1]));
}
__device__ __forceinline__ float sigmoidf_(float x) { return 1.0f / (1.0f + expf(-x)); }
__device__ __forceinline__ void sp2(bf16* H, bf16* L, int i, float a, float b) {
    bf16 ha = __float2bfloat16(a), hb = __float2bfloat16(b);
    bf162 hv; hv.x = ha; hv.y = hb;
    bf162 lv; lv.x = __float2bfloat16(a - __bfloat162float(ha));
    lv.y = __float2bfloat16(b - __bfloat162float(hb));
    *(bf162*)&H[i] = hv; *(bf162*)&L[i] = lv;
}
__device__ __forceinline__ void sp2h(__half* H, __half* L, int i, float a, float b) {
    __half ha = __float2half_rn(a), hb = __float2half_rn(b);
    __half2 hv; hv.x = ha; hv.y = hb;
    __half2 lv; lv.x = __float2half_rn(a - __half2float(ha));
    lv.y = __float2half_rn(b - __half2float(hb));
    *(__half2*)&H[i] = hv; *(__half2*)&L[i] = lv;
}

// ---- split-3 bf16 mma GEMM (init only): D[TM x TN] = A[TM,K] @ B[N,K]^T ----
#define ROWB 80
template<int TM, int TN, typename Epi>
__device__ __forceinline__ void mma_gemm(
    const bf16* __restrict__ Ah, const bf16* __restrict__ Al, int lda, int m0,
    const bf16* __restrict__ Bh, const bf16* __restrict__ Bl, int ldb, int n0,
    int K, Epi epi)
{
    extern __shared__ char smem[];
    constexpr int ASZ = TM * ROWB, BSZ = TN * ROWB, STG = 2*ASZ + 2*BSZ;
    constexpr int WM = TM / 4, WN = TN / 2, FM = WM / 16, NF = WN / 8;
    constexpr int GG = (NF > 4) ? 4 : NF;
    const uint32_t s0 = smem_u32(smem);
    const int tid = threadIdx.x, lane = tid & 31, wid = tid >> 5;
    const int wm = wid >> 1, wn = wid & 1;
    const int lrow = lane & 15, lhalf = lane >> 4;
    float acc[FM][NF][4] = {};

    auto issue = [&](int ch, int st) {
        uint32_t d = s0 + st * STG;
        int k0 = ch * 32;
        #pragma unroll
        for (int v = tid; v < TM * 4; v += 256) {
            int row = v >> 2, c = v & 3;
            cpasync16(d + row*ROWB + c*16,       Ah + (m0+row)*lda + k0 + c*8);
            cpasync16(d + ASZ + row*ROWB + c*16, Al + (m0+row)*lda + k0 + c*8);
        }
        #pragma unroll
        for (int v = tid; v < TN * 4; v += 256) {
            int row = v >> 2, c = v & 3;
            cpasync16(d + 2*ASZ + row*ROWB + c*16,       Bh + (n0+row)*ldb + k0 + c*8);
            cpasync16(d + 2*ASZ + BSZ + row*ROWB + c*16, Bl + (n0+row)*ldb + k0 + c*8);
        }
        CP_COMMIT();
    };

    const int NC = K / 32;
    issue(0, 0);
    for (int ch = 0; ch < NC; ch++) {
        int st = ch & 1;
        if (ch + 1 < NC) { issue(ch + 1, (ch + 1) & 1); CP_WAIT1(); }
        else CP_WAIT0();
        __syncthreads();
        uint32_t d = s0 + st * STG;
        #pragma unroll
        for (int kk = 0; kk < 2; kk++) {
            uint32_t ah[FM][4], al[FM][4];
            #pragma unroll
            for (int f = 0; f < FM; f++) {
                uint32_t a = d + (wm*WM + f*16 + lrow)*ROWB + lhalf*16 + kk*32;
                LDSM4(ah[f], a);
                LDSM4(al[f], a + ASZ);
            }
            #pragma unroll
            for (int gg = 0; gg < NF; gg += GG) {
                uint32_t bh[GG][2], bl[GG][2];
                #pragma unroll
                for (int g2 = 0; g2 < GG; g2 += 2) {
                    int g = gg + g2;
                    uint32_t b = d + 2*ASZ + (wn*WN + g*8 + lrow)*ROWB + lhalf*16 + kk*32;
                    uint32_t t4[4];
                    LDSM4(t4, b);
                    bh[g2][0]=t4[0]; bh[g2][1]=t4[2]; bh[g2+1][0]=t4[1]; bh[g2+1][1]=t4[3];
                    LDSM4(t4, b + BSZ);
                    bl[g2][0]=t4[0]; bl[g2][1]=t4[2]; bl[g2+1][0]=t4[1]; bl[g2+1][1]=t4[3];
                }
                #pragma unroll
                for (int f = 0; f < FM; f++)
                    #pragma unroll
                    for (int g2 = 0; g2 < GG; g2++) {
                        mmaop(acc[f][gg+g2], ah[f], bh[g2]);
                        mmaop(acc[f][gg+g2], ah[f], bl[g2]);
                        mmaop(acc[f][gg+g2], al[f], bh[g2]);
                    }
            }
        }
        __syncthreads();
    }
    #pragma unroll
    for (int f = 0; f < FM; f++)
        #pragma unroll
        for (int g = 0; g < NF; g++) {
            int r = m0 + wm*WM + f*16 + (lane >> 2);
            int c = n0 + wn*WN + g*8 + (lane & 3)*2;
            epi(r,     c, acc[f][g][0], acc[f][g][1]);
            epi(r + 8, c, acc[f][g][2], acc[f][g][3]);
        }
}

// ---- 2-term fp16 GEMM: D = (Ah+Al)[TM,K] @ Bh[N,K]^T ----
template<int TM, int TN, typename Epi>
__device__ __forceinline__ void mma_gemm_h2(
    const __half* __restrict__ Ah, const __half* __restrict__ Al, int lda, int m0,
    const __half* __restrict__ Bh, int ldb, int n0, int K, Epi epi)
{
    extern __shared__ char smem[];
    constexpr int ASZ = TM * ROWB, BSZ = TN * ROWB, STG = 2*ASZ + BSZ;
    constexpr int WM = TM / 4, WN = TN / 2, FM = WM / 16, NF = WN / 8;
    constexpr int GG = (NF > 4) ? 4 : NF;
    const uint32_t s0 = smem_u32(smem);
    const int tid = threadIdx.x, lane = tid & 31, wid = tid >> 5;
    const int wm = wid >> 1, wn = wid & 1;
    const int lrow = lane & 15, lhalf = lane >> 4;
    float acc[FM][NF][4] = {};

    auto issue = [&](int ch, int st) {
        uint32_t d = s0 + st * STG;
        int k0 = ch * 32;
        #pragma unroll
        for (int v = tid; v < TM * 4; v += 256) {
            int row = v >> 2, c = v & 3;
            cpasync16(d + row*ROWB + c*16,       Ah + (m0+row)*lda + k0 + c*8);
            cpasync16(d + ASZ + row*ROWB + c*16, Al + (m0+row)*lda + k0 + c*8);
        }
        #pragma unroll
        for (int v = tid; v < TN * 4; v += 256) {
            int row = v >> 2, c = v & 3;
            cpasync16(d + 2*ASZ + row*ROWB + c*16, Bh + (n0+row)*ldb + k0 + c*8);
        }
        CP_COMMIT();
    };

    const int NC = K / 32;
    issue(0, 0);
    for (int ch = 0; ch < NC; ch++) {
        int st = ch & 1;
        if (ch + 1 < NC) { issue(ch + 1, (ch + 1) & 1); CP_WAIT1(); }
        else CP_WAIT0();
        __syncthreads();
        uint32_t d = s0 + st * STG;
        #pragma unroll
        for (int kk = 0; kk < 2; kk++) {
            uint32_t ah[FM][4], al[FM][4];
            #pragma unroll
            for (int f = 0; f < FM; f++) {
                uint32_t a = d + (wm*WM + f*16 + lrow)*ROWB + lhalf*16 + kk*32;
                LDSM4(ah[f], a);
                LDSM4(al[f], a + ASZ);
            }
            #pragma unroll
            for (int gg = 0; gg < NF; gg += GG) {
                uint32_t bh[GG][2];
                #pragma unroll
                for (int g2 = 0; g2 < GG; g2 += 2) {
                    int g = gg + g2;
                    uint32_t b = d + 2*ASZ + (wn*WN + g*8 + lrow)*ROWB + lhalf*16 + kk*32;
                    uint32_t t4[4];
                    LDSM4(t4, b);
                    bh[g2][0]=t4[0]; bh[g2][1]=t4[2]; bh[g2+1][0]=t4[1]; bh[g2+1][1]=t4[3];
                }
                #pragma unroll
                for (int f = 0; f < FM; f++)
                    #pragma unroll
                    for (int g2 = 0; g2 < GG; g2++) {
                        mmaop_h(acc[f][gg+g2], ah[f], bh[g2]);
                        mmaop_h(acc[f][gg+g2], al[f], bh[g2]);
                    }
            }
        }
        __syncthreads();
    }
    #pragma unroll
    for (int f = 0; f < FM; f++)
        #pragma unroll
        for (int g = 0; g < NF; g++) {
            int r = m0 + wm*WM + f*16 + (lane >> 2);
            int c = n0 + wn*WN + g*8 + (lane & 3)*2;
            epi(r,     c, acc[f][g][0], acc[f][g][1]);
            epi(r + 8, c, acc[f][g][2], acc[f][g][3]);
        }
}
#define SMEM_S  (2 * (2*64*ROWB + 2*32*ROWB))      // 30720 (64x32 3-term)
#define SM66H   (2 * (2*64*ROWB + 64*ROWB))        // 30720 (64x64 2-term)
#define SMEM_H  (2 * (2*128*ROWB + 128*ROWB))      // 61440 (128x128 2-term)

// ---- prepack ----
__global__ __launch_bounds__(256) void pk_T(const float* __restrict__ src,
                                            bf16* __restrict__ dh, bf16* __restrict__ dl,
                                            int K, int N)
{
    __shared__ float tile[32][33];
    int kb = blockIdx.y * 32, nb = blockIdx.x * 32;
    int tx = threadIdx.x & 31, ty = threadIdx.x >> 5;
    for (int i = ty; i < 32; i += 8)
        tile[i][tx] = src[(kb + i) * N + nb + tx];
    __syncthreads();
    for (int i = ty; i < 32; i += 8) {
        int n = nb + i, k = kb + tx;
        float x = tile[tx][i];
        bf16 h = __float2bfloat16(x);
        dh[n * K + k] = h;
        dl[n * K + k] = __float2bfloat16(x - __bfloat162float(h));
    }
}
__global__ __launch_bounds__(256) void pk_gruH(const float* __restrict__ Wu,
                                               const float* __restrict__ Wr,
                                               const float* __restrict__ Wc)
{
    __shared__ float tile[32][33];
    int z = blockIdx.z;
    int gate = (z < 3) ? z : z - 3, layer = z / 3;
    const float* src = ((gate == 0) ? Wu : (gate == 1) ? Wr : Wc) + layer * 1024 * Hh;
    int kb = blockIdx.y * 32, nb = blockIdx.x * 32;
    int tx = threadIdx.x & 31, ty = threadIdx.x >> 5;
    for (int i = ty; i < 32; i += 8)
        tile[i][tx] = src[(kb + i) * Hh + nb + tx];
    __syncthreads();
    for (int i = ty; i < 32; i += 8)
        g_WgruH[z*SZGRU + (nb + i) * 1024 + kb + tx] = __float2half_rn(tile[tx][i]);
}
__global__ __launch_bounds__(256) void pk_Wo(const float* __restrict__ src)
{
    __shared__ float tile[32][33];
    int kb = blockIdx.y * 32, nb = blockIdx.x * 32;
    int tx = threadIdx.x & 31, ty = threadIdx.x >> 5;
    for (int i = ty; i < 32; i += 8) {
        int n = nb + tx;
        tile[i][tx] = (n < Vv) ? src[(kb + i) * Vv + n] : 0.f;
    }
    __syncthreads();
    for (int i = ty; i < 32; i += 8)
        g_WoH[(nb + i) * Hh + kb + tx] = __float2half_rn(tile[tx][i]);
}
__global__ __launch_bounds__(256) void pk_vgg(const float* __restrict__ src)
{
    int i = (blockIdx.x * 256 + threadIdx.x) * 2;
    sp2(g_vgg_h, g_vgg_l, i, src[i], src[i + 1]);
}
__global__ __launch_bounds__(256) void k_gather(const float* __restrict__ emb,
                                                const int* __restrict__ tok)
{
    int idx = (blockIdx.x * 256 + threadIdx.x) * 2;
    int r = idx >> 9, e = idx & 511;
    int token = tok[(r & 127) * Tt + (r >> 7)];
    sp2h(g_xembH, g_xembL, idx, emb[token * Hh + e], emb[token * Hh + e + 1]);
}

// ---- init: split-K partials then finalize ----
__global__ __launch_bounds__(256, 1) void k_initp()
{
    int cta = blockIdx.x;
    int ks = cta >> 5, mt = (cta >> 4) & 1, nt = cta & 15;
    int koff = ks * 1024;
    float* out = g_ipart[ks];
    mma_gemm<64,32>(g_vgg_h + koff, g_vgg_l + koff, Ff, mt*64,
                    g_Win_h + koff, g_Win_l + koff, Ff, nt*32, 1024,
        [&](int r, int c, float v0, float v1) {
            out[r*Hh + c] = v0; out[r*Hh + c + 1] = v1;
        });
}
__global__ __launch_bounds__(256) void k_initf(const float* __restrict__ b_in)
{
    int i = (blockIdx.x * 256 + threadIdx.x) * 2;
    float v0 = tanhf(g_ipart[0][i] + g_ipart[1][i] + g_ipart[2][i] + g_ipart[3][i]
                     + b_in[i & 511]);
    float v1 = tanhf(g_ipart[0][i+1] + g_ipart[1][i+1] + g_ipart[2][i+1] + g_ipart[3][i+1]
                     + b_in[(i+1) & 511]);
    g_h0f[i] = v0; g_h0f[i+1] = v1;
    g_h1f[i] = v0; g_h1f[i+1] = v1;
    sp2h(g_h0H, g_h0L, i, v0, v1);
    int ci = (i >> 9) * 1024 + 512 + (i & 511);
    sp2h(g_c1H, g_c1L, ci, v0, v1);
}

// ---- layer0 x-projections for all t (128x128, 2-term fp16) ----
__global__ __launch_bounds__(256, 2) void k_xpre(const float* __restrict__ bu,
                                                 const float* __restrict__ br,
                                                 const float* __restrict__ bc)
{
    int n0 = blockIdx.x * 128, m0 = blockIdx.y * 128, gate = blockIdx.z;
    const float* bi = (gate == 0) ? bu : (gate == 1) ? br : bc;
    float* out = (gate == 0) ? g_Xu0 : (gate == 1) ? g_Xr0 : g_Xc0;
    mma_gemm_h2<128,128>(g_xembH, g_xembL, Hh, m0,
                         g_WgruH + gate*SZGRU, 1024, n0, Hh,
        [&](int r, int c, float v0, float v1) {
            float2 val = make_float2(v0 + bi[c], v1 + bi[c + 1]);
            *(float2*)&out[r*Hh + c] = val;
        });
}

// ---- wave UR: z={0,1}: layer0 u/r @t=w ; z={2,3}: layer1 u/r @t=w-1 ----
__global__ __launch_bounds__(256, 1) void k_ur(int w,
                                               const float* __restrict__ bu1,
                                               const float* __restrict__ br1)
{
    int nt = blockIdx.x, mt = blockIdx.y, z = blockIdx.z;
    int n0 = nt * 64;
    if (z < 2) {
        if (w >= Tt) return;
        int gate = z;
        const float* X = (gate ? g_Xr0 : g_Xu0) + w * BH;
        mma_gemm_h2<64,64>(g_h0H, g_h0L, Hh, mt*64,
            g_WgruH + gate*SZGRU + 512, 1024, n0, Hh,
            [&](int r, int c, float v0, float v1) {
                int idx = r*Hh + c;
                float s0 = sigmoidf_(v0 + X[idx]);
                float s1 = sigmoidf_(v1 + X[idx+1]);
                if (gate == 0) { g_u0f[idx] = s0; g_u0f[idx+1] = s1; }
                else sp2h(g_rh0H, g_rh0L, idx, s0*g_h0f[idx], s1*g_h0f[idx+1]);
            });
    } else {
        if (w == 0) return;
        int gate = z - 2, par = (w - 1) & 1;
        const float* bi = gate ? br1 : bu1;
        mma_gemm_h2<64,64>(g_c1H, g_c1L, 1024, mt*64,
            g_WgruH + (3+gate)*SZGRU, 1024, n0, 1024,
            [&](int r, int c, float v0, float v1) {
                int idx = r*Hh + c;
                float s0 = sigmoidf_(v0 + bi[c]);
                float s1 = sigmoidf_(v1 + bi[c+1]);
                if (gate == 0) { g_u1f[idx] = s0; g_u1f[idx+1] = s1; }
                else sp2h(g_c2H[par], g_c2L[par], r*1024 + 512 + c,
                          s0*g_h1f[idx], s1*g_h1f[idx+1]);
            });
    }
}

// ---- wave C: z=0: layer0 cand+update @t=w ; z=1: layer1 @t=w-1 ----
__global__ __launch_bounds__(256, 1) void k_c(int w, const float* __restrict__ bc1)
{
    int nt = blockIdx.x, mt = blockIdx.y, z = blockIdx.z;
    int n0 = nt * 64;
    if (z == 0) {
        if (w >= Tt) return;
        int par = w & 1;
        const float* Xc = g_Xc0 + w * BH;
        mma_gemm_h2<64,64>(g_rh0H, g_rh0L, Hh, mt*64,
            g_WgruH + 2*SZGRU + 512, 1024, n0, Hh,
            [&](int r, int c, float v0, float v1) {
                int idx = r*Hh + c;
                float c0 = tanhf(v0 + Xc[idx]), c1 = tanhf(v1 + Xc[idx+1]);
                float u0 = g_u0f[idx], u1 = g_u0f[idx+1];
                float h0 = u0*g_h0f[idx]   + (1.f-u0)*c0;
                float h1 = u1*g_h0f[idx+1] + (1.f-u1)*c1;
                g_h0f[idx] = h0; g_h0f[idx+1] = h1;
                sp2h(g_h0H, g_h0L, idx, h0, h1);
                int ci = r*1024 + c;
                sp2h(g_c1H, g_c1L, ci, h0, h1);
                sp2h(g_c2H[par], g_c2L[par], ci, h0, h1);
            });
    } else {
        if (w == 0) return;
        int par = (w - 1) & 1;
        mma_gemm_h2<64,64>(g_c2H[par], g_c2L[par], 1024, mt*64,
            g_WgruH + 5*SZGRU, 1024, n0, 1024,
            [&](int r, int c, float v0, float v1) {
                int idx = r*Hh + c;
                float c0 = tanhf(v0 + bc1[c]), c1 = tanhf(v1 + bc1[c+1]);
                float u0 = g_u1f[idx], u1 = g_u1f[idx+1];
                float h0 = u0*g_h1f[idx]   + (1.f-u0)*c0;
                float h1 = u1*g_h1f[idx+1] + (1.f-u1)*c1;
                g_h1f[idx] = h0; g_h1f[idx+1] = h1;
                sp2h(g_c1H, g_c1L, r*1024 + 512 + c, h0, h1);
                sp2h(g_X1ah, g_X1al, ((w-1)*Bb + r)*Hh + c, h0, h1);
            });
    }
}

// ---- logits: 2-term fp16 (standalone, as round 9) ----
__global__ __launch_bounds__(256, 2) void k_logits(const float* __restrict__ bout,
                                                   float* __restrict__ out)
{
    int n0 = blockIdx.x * 128, m0 = blockIdx.y * 128;
    mma_gemm_h2<128,128>(g_X1ah, g_X1al, Hh, m0, g_WoH, Hh, n0, Hh,
        [&](int r, int c, float v0, float v1) {
            if (c < Vv) {
                int t = r >> 7, b = r & 127;
                long long base = (long long)(b * Tt + t) * Vv;
                out[base + c] = v0 + bout[c];
                if (c + 1 < Vv) out[base + c + 1] = v1 + bout[c + 1];
            }
        });
}

__global__ __launch_bounds__(256) void k_final(float* __restrict__ out)
{
    int i = blockIdx.x * 256 + threadIdx.x;
    out[(long long)Bb * Tt * Vv + i] = (i >> 16) ? g_h1f[i & (BH-1)] : g_h0f[i & (BH-1)];
}

// ---- launch ----
extern "C" void kernel_launch(void* const* d_in, const int* in_sizes, int n_in,
                              void* d_out, int out_size)
{
    const float* vgg   = (const float*)d_in[0];
    const int*   xTok  = (const int*)  d_in[1];
    const float* emb   = (const float*)d_in[2];
    const float* W_in  = (const float*)d_in[3];
    const float* b_in  = (const float*)d_in[4];
    const float* Wu    = (const float*)d_in[5];
    const float* bu    = (const float*)d_in[6];
    const float* Wr    = (const float*)d_in[7];
    const float* br    = (const float*)d_in[8];
    const float* Wc    = (const float*)d_in[9];
    const float* bc    = (const float*)d_in[10];
    const float* W_out = (const float*)d_in[11];
    const float* b_out = (const float*)d_in[12];
    float* out = (float*)d_out;

    cudaFuncSetAttribute(k_xpre,   cudaFuncAttributeMaxDynamicSharedMemorySize, SMEM_H);
    cudaFuncSetAttribute(k_logits, cudaFuncAttributeMaxDynamicSharedMemorySize, SMEM_H);

    bf16 *Wih, *Wil;
    cudaGetSymbolAddress((void**)&Wih, g_Win_h);
    cudaGetSymbolAddress((void**)&Wil, g_Win_l);

    pk_vgg<<<(Bb*Ff/2)/256, 256>>>(vgg);
    pk_T<<<dim3(16, 128), 256>>>(W_in, Wih, Wil, Ff, Hh);
    pk_gruH<<<dim3(16, 32, 6), 256>>>(Wu, Wr, Wc);
    pk_Wo<<<dim3(Vpad/32, 16), 256>>>(W_out);

    k_initp<<<128, 256, SMEM_S>>>();
    k_initf<<<(BH/2)/256, 256>>>(b_in);
    k_gather<<<(TBH/2)/256, 256>>>(emb, xTok);
    k_xpre<<<dim3(4, Tt*Bb/128, 3), 256, SMEM_H>>>(bu, br, bc);

    for (int w = 0; w <= Tt; w++) {
        k_ur<<<dim3(8, 2, 4), 256, SM66H>>>(w, bu + Hh, br + Hh);
        k_c <<<dim3(8, 2, 2), 256, SM66H>>>(w, bc + Hh);
    }

    k_logits<<<dim3(Vpad/128, Tt*Bb/128), 256, SMEM_H>>>(b_out, out);
    k_final<<<(2*BH)/256, 256>>>(out);
}

// round 12
// speedup vs baseline: 1.2621x; 1.2553x over previous
#include <cuda_runtime.h>
#include <cuda_bf16.h>
#include <cuda_fp16.h>
#include <math.h>
#include <stdint.h>

#define Bb 128
#define Tt 30
#define Vv 10000
#define Hh 512
#define Ff 4096
#define BH (Bb*Hh)
#define TBH (Tt*Bb*Hh)
#define Vpad 10112
#define SZGRU (512*1024)

typedef __nv_bfloat16 bf16;
typedef __nv_bfloat162 bf162;

__device__ float g_h0f[BH], g_h1f[BH], g_u0f[BH], g_u1f[BH];
__device__ float g_Xu0[TBH], g_Xr0[TBH], g_Xc0[TBH];
__device__ float g_ipart[4][BH];

// bf16 operands (init GEMM only)
__device__ __align__(16) bf16 g_vgg_h[Bb*Ff], g_vgg_l[Bb*Ff];
__device__ __align__(16) bf16 g_Win_h[Hh*Ff], g_Win_l[Hh*Ff];

// fp16 hi/lo activations (scan + xpre + logits)
__device__ __align__(16) __half g_xembH[TBH], g_xembL[TBH];
__device__ __align__(16) __half g_h0H[BH], g_h0L[BH];
__device__ __align__(16) __half g_rh0H[BH], g_rh0L[BH];
__device__ __align__(16) __half g_c1H[Bb*1024], g_c1L[Bb*1024];
__device__ __align__(16) __half g_c2H[2][Bb*1024], g_c2L[2][Bb*1024];
__device__ __align__(16) __half g_X1ah[TBH], g_X1al[TBH];

// fp16 single weights
__device__ __align__(16) __half g_WgruH[6*SZGRU];   // [z][N=512, K=1024]
__device__ __align__(16) __half g_WoH[Vpad*Hh];     // [N, K=512]

__device__ __forceinline__ uint32_t smem_u32(const void* p) {
    uint32_t a;
    asm("{ .reg .u64 t; cvta.to.shared.u64 t, %1; cvt.u32.u64 %0, t; }" : "=r"(a) : "l"(p));
    return a;
}
__device__ __forceinline__ void cpasync16(uint32_t dst, const void* src) {
    asm volatile("cp.async.cg.shared.global [%0], [%1], 16;" :: "r"(dst), "l"(src) : "memory");
}
#define CP_COMMIT() asm volatile("cp.async.commit_group;" ::: "memory")
#define CP_WAIT1()  asm volatile("cp.async.wait_group 1;" ::: "memory")
#define CP_WAIT0()  asm volatile("cp.async.wait_group 0;" ::: "memory")
#define LDSM4(R, addr) \
    asm volatile("ldmatrix.sync.aligned.m8n8.x4.shared.b16 {%0,%1,%2,%3}, [%4];" \
        : "=r"((R)[0]), "=r"((R)[1]), "=r"((R)[2]), "=r"((R)[3]) : "r"(addr))

__device__ __forceinline__ void mmaop(float* c, const uint32_t* a, const uint32_t* b) {
    asm volatile("mma.sync.aligned.m16n8k16.row.col.f32.bf16.bf16.f32 "
        "{%0,%1,%2,%3}, {%4,%5,%6,%7}, {%8,%9}, {%0,%1,%2,%3};"
        : "+f"(c[0]), "+f"(c[1]), "+f"(c[2]), "+f"(c[3])
        : "r"(a[0]), "r"(a[1]), "r"(a[2]), "r"(a[3]), "r"(b[0]), "r"(b[1]));
}
__device__ __forceinline__ void mmaop_h(float* c, const uint32_t* a, const uint32_t* b) {
    asm volatile("mma.sync.aligned.m16n8k16.row.col.f32.f16.f16.f32 "
        "{%0,%1,%2,%3}, {%4,%5,%6,%7}, {%8,%9}, {%0,%1,%2,%3};"
        : "+f"(c[0]), "+f"(c[1]), "+f"(c[2]), "+f"(c[3])
        : "r"(a[0]), "r"(a[1]), "r"(a[2]), "r"(a[3]), "r"(b[0]), "r"(b[1]));
}
__device__ __forceinline__ float sigmoidf_(float x) { return 1.0f / (1.0f + expf(-x)); }
__device__ __forceinline__ void sp2(bf16* H, bf16* L, int i, float a, float b) {
    bf16 ha = __float2bfloat16(a), hb = __float2bfloat16(b);
    bf162 hv; hv.x = ha; hv.y = hb;
    bf162 lv; lv.x = __float2bfloat16(a - __bfloat162float(ha));
    lv.y = __float2bfloat16(b - __bfloat162float(hb));
    *(bf162*)&H[i] = hv; *(bf162*)&L[i] = lv;
}
__device__ __forceinline__ void sp2h(__half* H, __half* L, int i, float a, float b) {
    __half ha = __float2half_rn(a), hb = __float2half_rn(b);
    __half2 hv; hv.x = ha; hv.y = hb;
    __half2 lv; lv.x = __float2half_rn(a - __half2float(ha));
    lv.y = __float2half_rn(b - __half2float(hb));
    *(__half2*)&H[i] = hv; *(__half2*)&L[i] = lv;
}

// ---- split-3 bf16 mma GEMM (init only): D[TM x TN] = A[TM,K] @ B[N,K]^T ----
#define ROWB 80
template<int TM, int TN, typename Epi>
__device__ __forceinline__ void mma_gemm(
    const bf16* __restrict__ Ah, const bf16* __restrict__ Al, int lda, int m0,
    const bf16* __restrict__ Bh, const bf16* __restrict__ Bl, int ldb, int n0,
    int K, Epi epi)
{
    extern __shared__ char smem[];
    constexpr int ASZ = TM * ROWB, BSZ = TN * ROWB, STG = 2*ASZ + 2*BSZ;
    constexpr int WM = TM / 4, WN = TN / 2, FM = WM / 16, NF = WN / 8;
    constexpr int GG = (NF > 4) ? 4 : NF;
    const uint32_t s0 = smem_u32(smem);
    const int tid = threadIdx.x, lane = tid & 31, wid = tid >> 5;
    const int wm = wid >> 1, wn = wid & 1;
    const int lrow = lane & 15, lhalf = lane >> 4;
    float acc[FM][NF][4] = {};

    auto issue = [&](int ch, int st) {
        uint32_t d = s0 + st * STG;
        int k0 = ch * 32;
        #pragma unroll
        for (int v = tid; v < TM * 4; v += 256) {
            int row = v >> 2, c = v & 3;
            cpasync16(d + row*ROWB + c*16,       Ah + (m0+row)*lda + k0 + c*8);
            cpasync16(d + ASZ + row*ROWB + c*16, Al + (m0+row)*lda + k0 + c*8);
        }
        #pragma unroll
        for (int v = tid; v < TN * 4; v += 256) {
            int row = v >> 2, c = v & 3;
            cpasync16(d + 2*ASZ + row*ROWB + c*16,       Bh + (n0+row)*ldb + k0 + c*8);
            cpasync16(d + 2*ASZ + BSZ + row*ROWB + c*16, Bl + (n0+row)*ldb + k0 + c*8);
        }
        CP_COMMIT();
    };

    const int NC = K / 32;
    issue(0, 0);
    for (int ch = 0; ch < NC; ch++) {
        int st = ch & 1;
        if (ch + 1 < NC) { issue(ch + 1, (ch + 1) & 1); CP_WAIT1(); }
        else CP_WAIT0();
        __syncthreads();
        uint32_t d = s0 + st * STG;
        #pragma unroll
        for (int kk = 0; kk < 2; kk++) {
            uint32_t ah[FM][4], al[FM][4];
            #pragma unroll
            for (int f = 0; f < FM; f++) {
                uint32_t a = d + (wm*WM + f*16 + lrow)*ROWB + lhalf*16 + kk*32;
                LDSM4(ah[f], a);
                LDSM4(al[f], a + ASZ);
            }
            #pragma unroll
            for (int gg = 0; gg < NF; gg += GG) {
                uint32_t bh[GG][2], bl[GG][2];
                #pragma unroll
                for (int g2 = 0; g2 < GG; g2 += 2) {
                    int g = gg + g2;
                    uint32_t b = d + 2*ASZ + (wn*WN + g*8 + lrow)*ROWB + lhalf*16 + kk*32;
                    uint32_t t4[4];
                    LDSM4(t4, b);
                    bh[g2][0]=t4[0]; bh[g2][1]=t4[2]; bh[g2+1][0]=t4[1]; bh[g2+1][1]=t4[3];
                    LDSM4(t4, b + BSZ);
                    bl[g2][0]=t4[0]; bl[g2][1]=t4[2]; bl[g2+1][0]=t4[1]; bl[g2+1][1]=t4[3];
                }
                #pragma unroll
                for (int f = 0; f < FM; f++)
                    #pragma unroll
                    for (int g2 = 0; g2 < GG; g2++) {
                        mmaop(acc[f][gg+g2], ah[f], bh[g2]);
                        mmaop(acc[f][gg+g2], ah[f], bl[g2]);
                        mmaop(acc[f][gg+g2], al[f], bh[g2]);
                    }
            }
        }
        __syncthreads();
    }
    #pragma unroll
    for (int f = 0; f < FM; f++)
        #pragma unroll
        for (int g = 0; g < NF; g++) {
            int r = m0 + wm*WM + f*16 + (lane >> 2);
            int c = n0 + wn*WN + g*8 + (lane & 3)*2;
            epi(r,     c, acc[f][g][0], acc[f][g][1]);
            epi(r + 8, c, acc[f][g][2], acc[f][g][3]);
        }
}

// ---- 2-term fp16 GEMM: D = (Ah+Al)[TM,K] @ Bh[N,K]^T ----
template<int TM, int TN, typename Epi>
__device__ __forceinline__ void mma_gemm_h2(
    const __half* __restrict__ Ah, const __half* __restrict__ Al, int lda, int m0,
    const __half* __restrict__ Bh, int ldb, int n0, int K, Epi epi)
{
    extern __shared__ char smem[];
    constexpr int ASZ = TM * ROWB, BSZ = TN * ROWB, STG = 2*ASZ + BSZ;
    constexpr int WM = TM / 4, WN = TN / 2, FM = WM / 16, NF = WN / 8;
    constexpr int GG = (NF > 4) ? 4 : NF;
    const uint32_t s0 = smem_u32(smem);
    const int tid = threadIdx.x, lane = tid & 31, wid = tid >> 5;
    const int wm = wid >> 1, wn = wid & 1;
    const int lrow = lane & 15, lhalf = lane >> 4;
    float acc[FM][NF][4] = {};

    auto issue = [&](int ch, int st) {
        uint32_t d = s0 + st * STG;
        int k0 = ch * 32;
        #pragma unroll
        for (int v = tid; v < TM * 4; v += 256) {
            int row = v >> 2, c = v & 3;
            cpasync16(d + row*ROWB + c*16,       Ah + (m0+row)*lda + k0 + c*8);
            cpasync16(d + ASZ + row*ROWB + c*16, Al + (m0+row)*lda + k0 + c*8);
        }
        #pragma unroll
        for (int v = tid; v < TN * 4; v += 256) {
            int row = v >> 2, c = v & 3;
            cpasync16(d + 2*ASZ + row*ROWB + c*16, Bh + (n0+row)*ldb + k0 + c*8);
        }
        CP_COMMIT();
    };

    const int NC = K / 32;
    issue(0, 0);
    for (int ch = 0; ch < NC; ch++) {
        int st = ch & 1;
        if (ch + 1 < NC) { issue(ch + 1, (ch + 1) & 1); CP_WAIT1(); }
        else CP_WAIT0();
        __syncthreads();
        uint32_t d = s0 + st * STG;
        #pragma unroll
        for (int kk = 0; kk < 2; kk++) {
            uint32_t ah[FM][4], al[FM][4];
            #pragma unroll
            for (int f = 0; f < FM; f++) {
                uint32_t a = d + (wm*WM + f*16 + lrow)*ROWB + lhalf*16 + kk*32;
                LDSM4(ah[f], a);
                LDSM4(al[f], a + ASZ);
            }
            #pragma unroll
            for (int gg = 0; gg < NF; gg += GG) {
                uint32_t bh[GG][2];
                #pragma unroll
                for (int g2 = 0; g2 < GG; g2 += 2) {
                    int g = gg + g2;
                    uint32_t b = d + 2*ASZ + (wn*WN + g*8 + lrow)*ROWB + lhalf*16 + kk*32;
                    uint32_t t4[4];
                    LDSM4(t4, b);
                    bh[g2][0]=t4[0]; bh[g2][1]=t4[2]; bh[g2+1][0]=t4[1]; bh[g2+1][1]=t4[3];
                }
                #pragma unroll
                for (int f = 0; f < FM; f++)
                    #pragma unroll
                    for (int g2 = 0; g2 < GG; g2++) {
                        mmaop_h(acc[f][gg+g2], ah[f], bh[g2]);
                        mmaop_h(acc[f][gg+g2], al[f], bh[g2]);
                    }
            }
        }
        __syncthreads();
    }
    #pragma unroll
    for (int f = 0; f < FM; f++)
        #pragma unroll
        for (int g = 0; g < NF; g++) {
            int r = m0 + wm*WM + f*16 + (lane >> 2);
            int c = n0 + wn*WN + g*8 + (lane & 3)*2;
            epi(r,     c, acc[f][g][0], acc[f][g][1]);
            epi(r + 8, c, acc[f][g][2], acc[f][g][3]);
        }
}
#define SMEM_S  (2 * (2*64*ROWB + 2*32*ROWB))      // 30720 (64x32 3-term)
#define SM63H   (2 * (2*64*ROWB + 32*ROWB))        // 25600 (64x32 2-term)
#define SMEM_H  (2 * (2*128*ROWB + 128*ROWB))      // 61440 (128x128 2-term)

// ---- prepack ----
__global__ __launch_bounds__(256) void pk_T(const float* __restrict__ src,
                                            bf16* __restrict__ dh, bf16* __restrict__ dl,
                                            int K, int N)
{
    __shared__ float tile[32][33];
    int kb = blockIdx.y * 32, nb = blockIdx.x * 32;
    int tx = threadIdx.x & 31, ty = threadIdx.x >> 5;
    for (int i = ty; i < 32; i += 8)
        tile[i][tx] = src[(kb + i) * N + nb + tx];
    __syncthreads();
    for (int i = ty; i < 32; i += 8) {
        int n = nb + i, k = kb + tx;
        float x = tile[tx][i];
        bf16 h = __float2bfloat16(x);
        dh[n * K + k] = h;
        dl[n * K + k] = __float2bfloat16(x - __bfloat162float(h));
    }
}
__global__ __launch_bounds__(256) void pk_gruH(const float* __restrict__ Wu,
                                               const float* __restrict__ Wr,
                                               const float* __restrict__ Wc)
{
    __shared__ float tile[32][33];
    int z = blockIdx.z;
    int gate = (z < 3) ? z : z - 3, layer = z / 3;
    const float* src = ((gate == 0) ? Wu : (gate == 1) ? Wr : Wc) + layer * 1024 * Hh;
    int kb = blockIdx.y * 32, nb = blockIdx.x * 32;
    int tx = threadIdx.x & 31, ty = threadIdx.x >> 5;
    for (int i = ty; i < 32; i += 8)
        tile[i][tx] = src[(kb + i) * Hh + nb + tx];
    __syncthreads();
    for (int i = ty; i < 32; i += 8)
        g_WgruH[z*SZGRU + (nb + i) * 1024 + kb + tx] = __float2half_rn(tile[tx][i]);
}
__global__ __launch_bounds__(256) void pk_Wo(const float* __restrict__ src)
{
    __shared__ float tile[32][33];
    int kb = blockIdx.y * 32, nb = blockIdx.x * 32;
    int tx = threadIdx.x & 31, ty = threadIdx.x >> 5;
    for (int i = ty; i < 32; i += 8) {
        int n = nb + tx;
        tile[i][tx] = (n < Vv) ? src[(kb + i) * Vv + n] : 0.f;
    }
    __syncthreads();
    for (int i = ty; i < 32; i += 8)
        g_WoH[(nb + i) * Hh + kb + tx] = __float2half_rn(tile[tx][i]);
}
__global__ __launch_bounds__(256) void pk_vgg(const float* __restrict__ src)
{
    int i = (blockIdx.x * 256 + threadIdx.x) * 2;
    sp2(g_vgg_h, g_vgg_l, i, src[i], src[i + 1]);
}
__global__ __launch_bounds__(256) void k_gather(const float* __restrict__ emb,
                                                const int* __restrict__ tok)
{
    int idx = (blockIdx.x * 256 + threadIdx.x) * 2;
    int r = idx >> 9, e = idx & 511;
    int token = tok[(r & 127) * Tt + (r >> 7)];
    sp2h(g_xembH, g_xembL, idx, emb[token * Hh + e], emb[token * Hh + e + 1]);
}

// ---- init: split-K partials then finalize ----
__global__ __launch_bounds__(256, 1) void k_initp()
{
    int cta = blockIdx.x;
    int ks = cta >> 5, mt = (cta >> 4) & 1, nt = cta & 15;
    int koff = ks * 1024;
    float* out = g_ipart[ks];
    mma_gemm<64,32>(g_vgg_h + koff, g_vgg_l + koff, Ff, mt*64,
                    g_Win_h + koff, g_Win_l + koff, Ff, nt*32, 1024,
        [&](int r, int c, float v0, float v1) {
            out[r*Hh + c] = v0; out[r*Hh + c + 1] = v1;
        });
}
__global__ __launch_bounds__(256) void k_initf(const float* __restrict__ b_in)
{
    int i = (blockIdx.x * 256 + threadIdx.x) * 2;
    float v0 = tanhf(g_ipart[0][i] + g_ipart[1][i] + g_ipart[2][i] + g_ipart[3][i]
                     + b_in[i & 511]);
    float v1 = tanhf(g_ipart[0][i+1] + g_ipart[1][i+1] + g_ipart[2][i+1] + g_ipart[3][i+1]
                     + b_in[(i+1) & 511]);
    g_h0f[i] = v0; g_h0f[i+1] = v1;
    g_h1f[i] = v0; g_h1f[i+1] = v1;
    sp2h(g_h0H, g_h0L, i, v0, v1);
    int ci = (i >> 9) * 1024 + 512 + (i & 511);
    sp2h(g_c1H, g_c1L, ci, v0, v1);
}

// ---- layer0 x-projections for all t (128x128, 2-term fp16) ----
__global__ __launch_bounds__(256, 2) void k_xpre(const float* __restrict__ bu,
                                                 const float* __restrict__ br,
                                                 const float* __restrict__ bc)
{
    int n0 = blockIdx.x * 128, m0 = blockIdx.y * 128, gate = blockIdx.z;
    const float* bi = (gate == 0) ? bu : (gate == 1) ? br : bc;
    float* out = (gate == 0) ? g_Xu0 : (gate == 1) ? g_Xr0 : g_Xc0;
    mma_gemm_h2<128,128>(g_xembH, g_xembL, Hh, m0,
                         g_WgruH + gate*SZGRU, 1024, n0, Hh,
        [&](int r, int c, float v0, float v1) {
            float2 val = make_float2(v0 + bi[c], v1 + bi[c + 1]);
            *(float2*)&out[r*Hh + c] = val;
        });
}

// ---- wave UR: z={0,1}: layer0 u/r @t=w ; z={2,3}: layer1 u/r @t=w-1 (64x32) ----
__global__ __launch_bounds__(256, 1) void k_ur(int w,
                                               const float* __restrict__ bu1,
                                               const float* __restrict__ br1)
{
    int nt = blockIdx.x, mt = blockIdx.y, z = blockIdx.z;
    int n0 = nt * 32;
    if (z < 2) {
        if (w >= Tt) return;
        int gate = z;
        const float* X = (gate ? g_Xr0 : g_Xu0) + w * BH;
        mma_gemm_h2<64,32>(g_h0H, g_h0L, Hh, mt*64,
            g_WgruH + gate*SZGRU + 512, 1024, n0, Hh,
            [&](int r, int c, float v0, float v1) {
                int idx = r*Hh + c;
                float s0 = sigmoidf_(v0 + X[idx]);
                float s1 = sigmoidf_(v1 + X[idx+1]);
                if (gate == 0) { g_u0f[idx] = s0; g_u0f[idx+1] = s1; }
                else sp2h(g_rh0H, g_rh0L, idx, s0*g_h0f[idx], s1*g_h0f[idx+1]);
            });
    } else {
        if (w == 0) return;
        int gate = z - 2, par = (w - 1) & 1;
        const float* bi = gate ? br1 : bu1;
        mma_gemm_h2<64,32>(g_c1H, g_c1L, 1024, mt*64,
            g_WgruH + (3+gate)*SZGRU, 1024, n0, 1024,
            [&](int r, int c, float v0, float v1) {
                int idx = r*Hh + c;
                float s0 = sigmoidf_(v0 + bi[c]);
                float s1 = sigmoidf_(v1 + bi[c+1]);
                if (gate == 0) { g_u1f[idx] = s0; g_u1f[idx+1] = s1; }
                else sp2h(g_c2H[par], g_c2L[par], r*1024 + 512 + c,
                          s0*g_h1f[idx], s1*g_h1f[idx+1]);
            });
    }
}

// ---- wave C: z=0: layer0 cand+update @t=w ; z=1: layer1 @t=w-1 (64x32) ----
__global__ __launch_bounds__(256, 1) void k_c(int w, const float* __restrict__ bc1)
{
    int nt = blockIdx.x, mt = blockIdx.y, z = blockIdx.z;
    int n0 = nt * 32;
    if (z == 0) {
        if (w >= Tt) return;
        int par = w & 1;
        const float* Xc = g_Xc0 + w * BH;
        mma_gemm_h2<64,32>(g_rh0H, g_rh0L, Hh, mt*64,
            g_WgruH + 2*SZGRU + 512, 1024, n0, Hh,
            [&](int r, int c, float v0, float v1) {
                int idx = r*Hh + c;
                float c0 = tanhf(v0 + Xc[idx]), c1 = tanhf(v1 + Xc[idx+1]);
                float u0 = g_u0f[idx], u1 = g_u0f[idx+1];
                float h0 = u0*g_h0f[idx]   + (1.f-u0)*c0;
                float h1 = u1*g_h0f[idx+1] + (1.f-u1)*c1;
                g_h0f[idx] = h0; g_h0f[idx+1] = h1;
                sp2h(g_h0H, g_h0L, idx, h0, h1);
                int ci = r*1024 + c;
                sp2h(g_c1H, g_c1L, ci, h0, h1);
                sp2h(g_c2H[par], g_c2L[par], ci, h0, h1);
            });
    } else {
        if (w == 0) return;
        int par = (w - 1) & 1;
        mma_gemm_h2<64,32>(g_c2H[par], g_c2L[par], 1024, mt*64,
            g_WgruH + 5*SZGRU, 1024, n0, 1024,
            [&](int r, int c, float v0, float v1) {
                int idx = r*Hh + c;
                float c0 = tanhf(v0 + bc1[c]), c1 = tanhf(v1 + bc1[c+1]);
                float u0 = g_u1f[idx], u1 = g_u1f[idx+1];
                float h0 = u0*g_h1f[idx]   + (1.f-u0)*c0;
                float h1 = u1*g_h1f[idx+1] + (1.f-u1)*c1;
                g_h1f[idx] = h0; g_h1f[idx+1] = h1;
                sp2h(g_c1H, g_c1L, r*1024 + 512 + c, h0, h1);
                sp2h(g_X1ah, g_X1al, ((w-1)*Bb + r)*Hh + c, h0, h1);
            });
    }
}

// ---- logits: 2-term fp16 ----
__global__ __launch_bounds__(256, 2) void k_logits(const float* __restrict__ bout,
                                                   float* __restrict__ out)
{
    int n0 = blockIdx.x * 128, m0 = blockIdx.y * 128;
    mma_gemm_h2<128,128>(g_X1ah, g_X1al, Hh, m0, g_WoH, Hh, n0, Hh,
        [&](int r, int c, float v0, float v1) {
            if (c < Vv) {
                int t = r >> 7, b = r & 127;
                long long base = (long long)(b * Tt + t) * Vv;
                out[base + c] = v0 + bout[c];
                if (c + 1 < Vv) out[base + c + 1] = v1 + bout[c + 1];
            }
        });
}

__global__ __launch_bounds__(256) void k_final(float* __restrict__ out)
{
    int i = blockIdx.x * 256 + threadIdx.x;
    out[(long long)Bb * Tt * Vv + i] = (i >> 16) ? g_h1f[i & (BH-1)] : g_h0f[i & (BH-1)];
}

// ---- launch ----
extern "C" void kernel_launch(void* const* d_in, const int* in_sizes, int n_in,
                              void* d_out, int out_size)
{
    const float* vgg   = (const float*)d_in[0];
    const int*   xTok  = (const int*)  d_in[1];
    const float* emb   = (const float*)d_in[2];
    const float* W_in  = (const float*)d_in[3];
    const float* b_in  = (const float*)d_in[4];
    const float* Wu    = (const float*)d_in[5];
    const float* bu    = (const float*)d_in[6];
    const float* Wr    = (const float*)d_in[7];
    const float* br    = (const float*)d_in[8];
    const float* Wc    = (const float*)d_in[9];
    const float* bc    = (const float*)d_in[10];
    const float* W_out = (const float*)d_in[11];
    const float* b_out = (const float*)d_in[12];
    float* out = (float*)d_out;

    cudaFuncSetAttribute(k_xpre,   cudaFuncAttributeMaxDynamicSharedMemorySize, SMEM_H);
    cudaFuncSetAttribute(k_logits, cudaFuncAttributeMaxDynamicSharedMemorySize, SMEM_H);

    bf16 *Wih, *Wil;
    cudaGetSymbolAddress((void**)&Wih, g_Win_h);
    cudaGetSymbolAddress((void**)&Wil, g_Win_l);

    pk_vgg<<<(Bb*Ff/2)/256, 256>>>(vgg);
    pk_T<<<dim3(16, 128), 256>>>(W_in, Wih, Wil, Ff, Hh);
    pk_gruH<<<dim3(16, 32, 6), 256>>>(Wu, Wr, Wc);
    pk_Wo<<<dim3(Vpad/32, 16), 256>>>(W_out);

    k_initp<<<128, 256, SMEM_S>>>();
    k_initf<<<(BH/2)/256, 256>>>(b_in);
    k_gather<<<(TBH/2)/256, 256>>>(emb, xTok);
    k_xpre<<<dim3(4, Tt*Bb/128, 3), 256, SMEM_H>>>(bu, br, bc);

    for (int w = 0; w <= Tt; w++) {
        k_ur<<<dim3(16, 2, 4), 256, SM63H>>>(w, bu + Hh, br + Hh);
        k_c <<<dim3(16, 2, 2), 256, SM63H>>>(w, bc + Hh);
    }

    k_logits<<<dim3(Vpad/128, Tt*Bb/128), 256, SMEM_H>>>(b_out, out);
    k_final<<<(2*BH)/256, 256>>>(out);
}

// round 13
// speedup vs baseline: 1.4338x; 1.1360x over previous
#include <cuda_runtime.h>
#include <cuda_bf16.h>
#include <cuda_fp16.h>
#include <math.h>
#include <stdint.h>

#define Bb 128
#define Tt 30
#define Vv 10000
#define Hh 512
#define Ff 4096
#define BH (Bb*Hh)
#define TBH (Tt*Bb*Hh)
#define Vpad 10112
#define SZGRU (512*1024)

typedef __nv_bfloat16 bf16;
typedef __nv_bfloat162 bf162;

__device__ float g_h0f[BH], g_h1f[BH], g_u0f[BH], g_u1f[BH];
__device__ float g_Xu0[TBH], g_Xr0[TBH], g_Xc0[TBH];
__device__ float g_ipart[4][BH];

// bf16 operands (init GEMM only)
__device__ __align__(16) bf16 g_vgg_h[Bb*Ff], g_vgg_l[Bb*Ff];
__device__ __align__(16) bf16 g_Win_h[Hh*Ff], g_Win_l[Hh*Ff];

// fp16 hi/lo activations
__device__ __align__(16) __half g_xembH[TBH], g_xembL[TBH];
__device__ __align__(16) __half g_h0H[BH], g_h0L[BH];
__device__ __align__(16) __half g_rh0H[BH], g_rh0L[BH];
__device__ __align__(16) __half g_c1H[Bb*1024], g_c1L[Bb*1024];
__device__ __align__(16) __half g_c2H[2][Bb*1024], g_c2L[2][Bb*1024];
__device__ __align__(16) __half g_X1ah[TBH], g_X1al[TBH];

// fp16 single weights
__device__ __align__(16) __half g_WgruH[6*SZGRU];   // [z][N=512, K=1024]
__device__ __align__(16) __half g_WoH[Vpad*Hh];     // [N, K=512]

__device__ __forceinline__ uint32_t smem_u32(const void* p) {
    uint32_t a;
    asm("{ .reg .u64 t; cvta.to.shared.u64 t, %1; cvt.u32.u64 %0, t; }" : "=r"(a) : "l"(p));
    return a;
}
__device__ __forceinline__ void cpasync16(uint32_t dst, const void* src) {
    asm volatile("cp.async.cg.shared.global [%0], [%1], 16;" :: "r"(dst), "l"(src) : "memory");
}
#define CP_COMMIT() asm volatile("cp.async.commit_group;" ::: "memory")
#define CP_WAIT2()  asm volatile("cp.async.wait_group 2;" ::: "memory")
#define CP_WAIT1()  asm volatile("cp.async.wait_group 1;" ::: "memory")
#define CP_WAIT0()  asm volatile("cp.async.wait_group 0;" ::: "memory")
#define LDSM4(R, addr) \
    asm volatile("ldmatrix.sync.aligned.m8n8.x4.shared.b16 {%0,%1,%2,%3}, [%4];" \
        : "=r"((R)[0]), "=r"((R)[1]), "=r"((R)[2]), "=r"((R)[3]) : "r"(addr))

__device__ __forceinline__ void mmaop(float* c, const uint32_t* a, const uint32_t* b) {
    asm volatile("mma.sync.aligned.m16n8k16.row.col.f32.bf16.bf16.f32 "
        "{%0,%1,%2,%3}, {%4,%5,%6,%7}, {%8,%9}, {%0,%1,%2,%3};"
        : "+f"(c[0]), "+f"(c[1]), "+f"(c[2]), "+f"(c[3])
        : "r"(a[0]), "r"(a[1]), "r"(a[2]), "r"(a[3]), "r"(b[0]), "r"(b[1]));
}
__device__ __forceinline__ void mmaop_h(float* c, const uint32_t* a, const uint32_t* b) {
    asm volatile("mma.sync.aligned.m16n8k16.row.col.f32.f16.f16.f32 "
        "{%0,%1,%2,%3}, {%4,%5,%6,%7}, {%8,%9}, {%0,%1,%2,%3};"
        : "+f"(c[0]), "+f"(c[1]), "+f"(c[2]), "+f"(c[3])
        : "r"(a[0]), "r"(a[1]), "r"(a[2]), "r"(a[3]), "r"(b[0]), "r"(b[1]));
}
__device__ __forceinline__ float sigmoidf_(float x) { return 1.0f / (1.0f + expf(-x)); }
__device__ __forceinline__ void sp2(bf16* H, bf16* L, int i, float a, float b) {
    bf16 ha = __float2bfloat16(a), hb = __float2bfloat16(b);
    bf162 hv; hv.x = ha; hv.y = hb;
    bf162 lv; lv.x = __float2bfloat16(a - __bfloat162float(ha));
    lv.y = __float2bfloat16(b - __bfloat162float(hb));
    *(bf162*)&H[i] = hv; *(bf162*)&L[i] = lv;
}
__device__ __forceinline__ void sp2h(__half* H, __half* L, int i, float a, float b) {
    __half ha = __float2half_rn(a), hb = __float2half_rn(b);
    __half2 hv; hv.x = ha; hv.y = hb;
    __half2 lv; lv.x = __float2half_rn(a - __half2float(ha));
    lv.y = __float2half_rn(b - __half2float(hb));
    *(__half2*)&H[i] = hv; *(__half2*)&L[i] = lv;
}

// ---- split-3 bf16 mma GEMM (init only), 2-stage KT=32 ----
#define ROWB 80
template<int TM, int TN, typename Epi>
__device__ __forceinline__ void mma_gemm(
    const bf16* __restrict__ Ah, const bf16* __restrict__ Al, int lda, int m0,
    const bf16* __restrict__ Bh, const bf16* __restrict__ Bl, int ldb, int n0,
    int K, Epi epi)
{
    extern __shared__ char smem[];
    constexpr int ASZ = TM * ROWB, BSZ = TN * ROWB, STG = 2*ASZ + 2*BSZ;
    constexpr int WM = TM / 4, WN = TN / 2, FM = WM / 16, NF = WN / 8;
    constexpr int GG = (NF > 4) ? 4 : NF;
    const uint32_t s0 = smem_u32(smem);
    const int tid = threadIdx.x, lane = tid & 31, wid = tid >> 5;
    const int wm = wid >> 1, wn = wid & 1;
    const int lrow = lane & 15, lhalf = lane >> 4;
    float acc[FM][NF][4] = {};

    auto issue = [&](int ch, int st) {
        uint32_t d = s0 + st * STG;
        int k0 = ch * 32;
        #pragma unroll
        for (int v = tid; v < TM * 4; v += 256) {
            int row = v >> 2, c = v & 3;
            cpasync16(d + row*ROWB + c*16,       Ah + (m0+row)*lda + k0 + c*8);
            cpasync16(d + ASZ + row*ROWB + c*16, Al + (m0+row)*lda + k0 + c*8);
        }
        #pragma unroll
        for (int v = tid; v < TN * 4; v += 256) {
            int row = v >> 2, c = v & 3;
            cpasync16(d + 2*ASZ + row*ROWB + c*16,       Bh + (n0+row)*ldb + k0 + c*8);
            cpasync16(d + 2*ASZ + BSZ + row*ROWB + c*16, Bl + (n0+row)*ldb + k0 + c*8);
        }
        CP_COMMIT();
    };

    const int NC = K / 32;
    issue(0, 0);
    for (int ch = 0; ch < NC; ch++) {
        int st = ch & 1;
        if (ch + 1 < NC) { issue(ch + 1, (ch + 1) & 1); CP_WAIT1(); }
        else CP_WAIT0();
        __syncthreads();
        uint32_t d = s0 + st * STG;
        #pragma unroll
        for (int kk = 0; kk < 2; kk++) {
            uint32_t ah[FM][4], al[FM][4];
            #pragma unroll
            for (int f = 0; f < FM; f++) {
                uint32_t a = d + (wm*WM + f*16 + lrow)*ROWB + lhalf*16 + kk*32;
                LDSM4(ah[f], a);
                LDSM4(al[f], a + ASZ);
            }
            #pragma unroll
            for (int gg = 0; gg < NF; gg += GG) {
                uint32_t bh[GG][2], bl[GG][2];
                #pragma unroll
                for (int g2 = 0; g2 < GG; g2 += 2) {
                    int g = gg + g2;
                    uint32_t b = d + 2*ASZ + (wn*WN + g*8 + lrow)*ROWB + lhalf*16 + kk*32;
                    uint32_t t4[4];
                    LDSM4(t4, b);
                    bh[g2][0]=t4[0]; bh[g2][1]=t4[2]; bh[g2+1][0]=t4[1]; bh[g2+1][1]=t4[3];
                    LDSM4(t4, b + BSZ);
                    bl[g2][0]=t4[0]; bl[g2][1]=t4[2]; bl[g2+1][0]=t4[1]; bl[g2+1][1]=t4[3];
                }
                #pragma unroll
                for (int f = 0; f < FM; f++)
                    #pragma unroll
                    for (int g2 = 0; g2 < GG; g2++) {
                        mmaop(acc[f][gg+g2], ah[f], bh[g2]);
                        mmaop(acc[f][gg+g2], ah[f], bl[g2]);
                        mmaop(acc[f][gg+g2], al[f], bh[g2]);
                    }
            }
        }
        __syncthreads();
    }
    #pragma unroll
    for (int f = 0; f < FM; f++)
        #pragma unroll
        for (int g = 0; g < NF; g++) {
            int r = m0 + wm*WM + f*16 + (lane >> 2);
            int c = n0 + wn*WN + g*8 + (lane & 3)*2;
            epi(r,     c, acc[f][g][0], acc[f][g][1]);
            epi(r + 8, c, acc[f][g][2], acc[f][g][3]);
        }
}

// ---- 2-term fp16 GEMM, 2-stage KT=32 (xpre / logits) ----
template<int TM, int TN, typename Epi>
__device__ __forceinline__ void mma_gemm_h2(
    const __half* __restrict__ Ah, const __half* __restrict__ Al, int lda, int m0,
    const __half* __restrict__ Bh, int ldb, int n0, int K, Epi epi)
{
    extern __shared__ char smem[];
    constexpr int ASZ = TM * ROWB, BSZ = TN * ROWB, STG = 2*ASZ + BSZ;
    constexpr int WM = TM / 4, WN = TN / 2, FM = WM / 16, NF = WN / 8;
    constexpr int GG = (NF > 4) ? 4 : NF;
    const uint32_t s0 = smem_u32(smem);
    const int tid = threadIdx.x, lane = tid & 31, wid = tid >> 5;
    const int wm = wid >> 1, wn = wid & 1;
    const int lrow = lane & 15, lhalf = lane >> 4;
    float acc[FM][NF][4] = {};

    auto issue = [&](int ch, int st) {
        uint32_t d = s0 + st * STG;
        int k0 = ch * 32;
        #pragma unroll
        for (int v = tid; v < TM * 4; v += 256) {
            int row = v >> 2, c = v & 3;
            cpasync16(d + row*ROWB + c*16,       Ah + (m0+row)*lda + k0 + c*8);
            cpasync16(d + ASZ + row*ROWB + c*16, Al + (m0+row)*lda + k0 + c*8);
        }
        #pragma unroll
        for (int v = tid; v < TN * 4; v += 256) {
            int row = v >> 2, c = v & 3;
            cpasync16(d + 2*ASZ + row*ROWB + c*16, Bh + (n0+row)*ldb + k0 + c*8);
        }
        CP_COMMIT();
    };

    const int NC = K / 32;
    issue(0, 0);
    for (int ch = 0; ch < NC; ch++) {
        int st = ch & 1;
        if (ch + 1 < NC) { issue(ch + 1, (ch + 1) & 1); CP_WAIT1(); }
        else CP_WAIT0();
        __syncthreads();
        uint32_t d = s0 + st * STG;
        #pragma unroll
        for (int kk = 0; kk < 2; kk++) {
            uint32_t ah[FM][4], al[FM][4];
            #pragma unroll
            for (int f = 0; f < FM; f++) {
                uint32_t a = d + (wm*WM + f*16 + lrow)*ROWB + lhalf*16 + kk*32;
                LDSM4(ah[f], a);
                LDSM4(al[f], a + ASZ);
            }
            #pragma unroll
            for (int gg = 0; gg < NF; gg += GG) {
                uint32_t bh[GG][2];
                #pragma unroll
                for (int g2 = 0; g2 < GG; g2 += 2) {
                    int g = gg + g2;
                    uint32_t b = d + 2*ASZ + (wn*WN + g*8 + lrow)*ROWB + lhalf*16 + kk*32;
                    uint32_t t4[4];
                    LDSM4(t4, b);
                    bh[g2][0]=t4[0]; bh[g2][1]=t4[2]; bh[g2+1][0]=t4[1]; bh[g2+1][1]=t4[3];
                }
                #pragma unroll
                for (int f = 0; f < FM; f++)
                    #pragma unroll
                    for (int g2 = 0; g2 < GG; g2++) {
                        mmaop_h(acc[f][gg+g2], ah[f], bh[g2]);
                        mmaop_h(acc[f][gg+g2], al[f], bh[g2]);
                    }
            }
        }
        __syncthreads();
    }
    #pragma unroll
    for (int f = 0; f < FM; f++)
        #pragma unroll
        for (int g = 0; g < NF; g++) {
            int r = m0 + wm*WM + f*16 + (lane >> 2);
            int c = n0 + wn*WN + g*8 + (lane & 3)*2;
            epi(r,     c, acc[f][g][0], acc[f][g][1]);
            epi(r + 8, c, acc[f][g][2], acc[f][g][3]);
        }
}

// ---- 2-term fp16 GEMM, 3-stage KT=64 (scan kernels) ----
#define ROWC 144
template<int TM, int TN, typename Epi>
__device__ __forceinline__ void mma_gemm_h3(
    const __half* __restrict__ Ah, const __half* __restrict__ Al, int lda, int m0,
    const __half* __restrict__ Bh, int ldb, int n0, int K, Epi epi)
{
    extern __shared__ char smem[];
    constexpr int ASZ = TM * ROWC, BSZ = TN * ROWC, STG = 2*ASZ + BSZ;
    constexpr int WM = TM / 4, WN = TN / 2, FM = WM / 16, NF = WN / 8;
    const uint32_t s0 = smem_u32(smem);
    const int tid = threadIdx.x, lane = tid & 31, wid = tid >> 5;
    const int wm = wid >> 1, wn = wid & 1;
    const int lrow = lane & 15, lhalf = lane >> 4;
    float acc[FM][NF][4] = {};

    auto issue = [&](int ch, int st) {
        uint32_t d = s0 + st * STG;
        int k0 = ch * 64;
        #pragma unroll
        for (int v = tid; v < TM * 8; v += 256) {
            int row = v >> 3, c = v & 7;
            cpasync16(d + row*ROWC + c*16,       Ah + (m0+row)*lda + k0 + c*8);
            cpasync16(d + ASZ + row*ROWC + c*16, Al + (m0+row)*lda + k0 + c*8);
        }
        #pragma unroll
        for (int v = tid; v < TN * 8; v += 256) {
            int row = v >> 3, c = v & 7;
            cpasync16(d + 2*ASZ + row*ROWC + c*16, Bh + (n0+row)*ldb + k0 + c*8);
        }
        CP_COMMIT();
    };

    const int NC = K / 64;          // >= 2 always here
    issue(0, 0);
    issue(1, 1);
    for (int ch = 0; ch < NC; ch++) {
        if (ch + 2 < NC) { issue(ch + 2, (ch + 2) % 3); CP_WAIT2(); }
        else if (ch + 1 < NC) CP_WAIT1();
        else CP_WAIT0();
        __syncthreads();
        uint32_t d = s0 + (ch % 3) * STG;
        #pragma unroll
        for (int kk = 0; kk < 4; kk++) {
            uint32_t ah[FM][4], al[FM][4], bh[NF][2];
            #pragma unroll
            for (int f = 0; f < FM; f++) {
                uint32_t a = d + (wm*WM + f*16 + lrow)*ROWC + lhalf*16 + kk*32;
                LDSM4(ah[f], a);
                LDSM4(al[f], a + ASZ);
            }
            #pragma unroll
            for (int g = 0; g < NF; g += 2) {
                uint32_t b = d + 2*ASZ + (wn*WN + g*8 + lrow)*ROWC + lhalf*16 + kk*32;
                uint32_t t4[4];
                LDSM4(t4, b);
                bh[g][0]=t4[0]; bh[g][1]=t4[2]; bh[g+1][0]=t4[1]; bh[g+1][1]=t4[3];
            }
            #pragma unroll
            for (int f = 0; f < FM; f++)
                #pragma unroll
                for (int g = 0; g < NF; g++) {
                    mmaop_h(acc[f][g], ah[f], bh[g]);
                    mmaop_h(acc[f][g], al[f], bh[g]);
                }
        }
        __syncthreads();
    }
    #pragma unroll
    for (int f = 0; f < FM; f++)
        #pragma unroll
        for (int g = 0; g < NF; g++) {
            int r = m0 + wm*WM + f*16 + (lane >> 2);
            int c = n0 + wn*WN + g*8 + (lane & 3)*2;
            epi(r,     c, acc[f][g][0], acc[f][g][1]);
            epi(r + 8, c, acc[f][g][2], acc[f][g][3]);
        }
}
#define SMEM_S  (2 * (2*64*ROWB + 2*32*ROWB))      // 30720 (init 3-term)
#define S3H     (3 * (2*64*ROWC + 32*ROWC))        // 69120 (scan 3-stage KT=64)
#define SMEM_H  (2 * (2*128*ROWB + 128*ROWB))      // 61440 (xpre/logits 2-term)

// ---- prepack ----
__global__ __launch_bounds__(256) void pk_T(const float* __restrict__ src,
                                            bf16* __restrict__ dh, bf16* __restrict__ dl,
                                            int K, int N)
{
    __shared__ float tile[32][33];
    int kb = blockIdx.y * 32, nb = blockIdx.x * 32;
    int tx = threadIdx.x & 31, ty = threadIdx.x >> 5;
    for (int i = ty; i < 32; i += 8)
        tile[i][tx] = src[(kb + i) * N + nb + tx];
    __syncthreads();
    for (int i = ty; i < 32; i += 8) {
        int n = nb + i, k = kb + tx;
        float x = tile[tx][i];
        bf16 h = __float2bfloat16(x);
        dh[n * K + k] = h;
        dl[n * K + k] = __float2bfloat16(x - __bfloat162float(h));
    }
}
__global__ __launch_bounds__(256) void pk_gruH(const float* __restrict__ Wu,
                                               const float* __restrict__ Wr,
                                               const float* __restrict__ Wc)
{
    __shared__ float tile[32][33];
    int z = blockIdx.z;
    int gate = (z < 3) ? z : z - 3, layer = z / 3;
    const float* src = ((gate == 0) ? Wu : (gate == 1) ? Wr : Wc) + layer * 1024 * Hh;
    int kb = blockIdx.y * 32, nb = blockIdx.x * 32;
    int tx = threadIdx.x & 31, ty = threadIdx.x >> 5;
    for (int i = ty; i < 32; i += 8)
        tile[i][tx] = src[(kb + i) * Hh + nb + tx];
    __syncthreads();
    for (int i = ty; i < 32; i += 8)
        g_WgruH[z*SZGRU + (nb + i) * 1024 + kb + tx] = __float2half_rn(tile[tx][i]);
}
__global__ __launch_bounds__(256) void pk_Wo(const float* __restrict__ src)
{
    __shared__ float tile[32][33];
    int kb = blockIdx.y * 32, nb = blockIdx.x * 32;
    int tx = threadIdx.x & 31, ty = threadIdx.x >> 5;
    for (int i = ty; i < 32; i += 8) {
        int n = nb + tx;
        tile[i][tx] = (n < Vv) ? src[(kb + i) * Vv + n] : 0.f;
    }
    __syncthreads();
    for (int i = ty; i < 32; i += 8)
        g_WoH[(nb + i) * Hh + kb + tx] = __float2half_rn(tile[tx][i]);
}
__global__ __launch_bounds__(256) void pk_vgg(const float* __restrict__ src)
{
    int i = (blockIdx.x * 256 + threadIdx.x) * 2;
    sp2(g_vgg_h, g_vgg_l, i, src[i], src[i + 1]);
}
__global__ __launch_bounds__(256) void k_gather(const float* __restrict__ emb,
                                                const int* __restrict__ tok)
{
    int idx = (blockIdx.x * 256 + threadIdx.x) * 2;
    int r = idx >> 9, e = idx & 511;
    int token = tok[(r & 127) * Tt + (r >> 7)];
    sp2h(g_xembH, g_xembL, idx, emb[token * Hh + e], emb[token * Hh + e + 1]);
}

// ---- init: split-K partials then finalize ----
__global__ __launch_bounds__(256, 1) void k_initp()
{
    int cta = blockIdx.x;
    int ks = cta >> 5, mt = (cta >> 4) & 1, nt = cta & 15;
    int koff = ks * 1024;
    float* out = g_ipart[ks];
    mma_gemm<64,32>(g_vgg_h + koff, g_vgg_l + koff, Ff, mt*64,
                    g_Win_h + koff, g_Win_l + koff, Ff, nt*32, 1024,
        [&](int r, int c, float v0, float v1) {
            out[r*Hh + c] = v0; out[r*Hh + c + 1] = v1;
        });
}
__global__ __launch_bounds__(256) void k_initf(const float* __restrict__ b_in)
{
    int i = (blockIdx.x * 256 + threadIdx.x) * 2;
    float v0 = tanhf(g_ipart[0][i] + g_ipart[1][i] + g_ipart[2][i] + g_ipart[3][i]
                     + b_in[i & 511]);
    float v1 = tanhf(g_ipart[0][i+1] + g_ipart[1][i+1] + g_ipart[2][i+1] + g_ipart[3][i+1]
                     + b_in[(i+1) & 511]);
    g_h0f[i] = v0; g_h0f[i+1] = v1;
    g_h1f[i] = v0; g_h1f[i+1] = v1;
    sp2h(g_h0H, g_h0L, i, v0, v1);
    int ci = (i >> 9) * 1024 + 512 + (i & 511);
    sp2h(g_c1H, g_c1L, ci, v0, v1);
}

// ---- layer0 x-projections for all t (128x128, 2-term fp16) ----
__global__ __launch_bounds__(256, 2) void k_xpre(const float* __restrict__ bu,
                                                 const float* __restrict__ br,
                                                 const float* __restrict__ bc)
{
    int n0 = blockIdx.x * 128, m0 = blockIdx.y * 128, gate = blockIdx.z;
    const float* bi = (gate == 0) ? bu : (gate == 1) ? br : bc;
    float* out = (gate == 0) ? g_Xu0 : (gate == 1) ? g_Xr0 : g_Xc0;
    mma_gemm_h2<128,128>(g_xembH, g_xembL, Hh, m0,
                         g_WgruH + gate*SZGRU, 1024, n0, Hh,
        [&](int r, int c, float v0, float v1) {
            float2 val = make_float2(v0 + bi[c], v1 + bi[c + 1]);
            *(float2*)&out[r*Hh + c] = val;
        });
}

// ---- wave UR: z={0,1}: layer0 u/r @t=w ; z={2,3}: layer1 u/r @t=w-1 (64x32, 3-stage) ----
__global__ __launch_bounds__(256, 1) void k_ur(int w,
                                               const float* __restrict__ bu1,
                                               const float* __restrict__ br1)
{
    int nt = blockIdx.x, mt = blockIdx.y, z = blockIdx.z;
    int n0 = nt * 32;
    if (z < 2) {
        if (w >= Tt) return;
        int gate = z;
        const float* X = (gate ? g_Xr0 : g_Xu0) + w * BH;
        mma_gemm_h3<64,32>(g_h0H, g_h0L, Hh, mt*64,
            g_WgruH + gate*SZGRU + 512, 1024, n0, Hh,
            [&](int r, int c, float v0, float v1) {
                int idx = r*Hh + c;
                float s0 = sigmoidf_(v0 + X[idx]);
                float s1 = sigmoidf_(v1 + X[idx+1]);
                if (gate == 0) { g_u0f[idx] = s0; g_u0f[idx+1] = s1; }
                else sp2h(g_rh0H, g_rh0L, idx, s0*g_h0f[idx], s1*g_h0f[idx+1]);
            });
    } else {
        if (w == 0) return;
        int gate = z - 2, par = (w - 1) & 1;
        const float* bi = gate ? br1 : bu1;
        mma_gemm_h3<64,32>(g_c1H, g_c1L, 1024, mt*64,
            g_WgruH + (3+gate)*SZGRU, 1024, n0, 1024,
            [&](int r, int c, float v0, float v1) {
                int idx = r*Hh + c;
                float s0 = sigmoidf_(v0 + bi[c]);
                float s1 = sigmoidf_(v1 + bi[c+1]);
                if (gate == 0) { g_u1f[idx] = s0; g_u1f[idx+1] = s1; }
                else sp2h(g_c2H[par], g_c2L[par], r*1024 + 512 + c,
                          s0*g_h1f[idx], s1*g_h1f[idx+1]);
            });
    }
}

// ---- wave C: z=0: layer0 cand+update @t=w ; z=1: layer1 @t=w-1 (64x32, 3-stage) ----
__global__ __launch_bounds__(256, 1) void k_c(int w, const float* __restrict__ bc1)
{
    int nt = blockIdx.x, mt = blockIdx.y, z = blockIdx.z;
    int n0 = nt * 32;
    if (z == 0) {
        if (w >= Tt) return;
        int par = w & 1;
        const float* Xc = g_Xc0 + w * BH;
        mma_gemm_h3<64,32>(g_rh0H, g_rh0L, Hh, mt*64,
            g_WgruH + 2*SZGRU + 512, 1024, n0, Hh,
            [&](int r, int c, float v0, float v1) {
                int idx = r*Hh + c;
                float c0 = tanhf(v0 + Xc[idx]), c1 = tanhf(v1 + Xc[idx+1]);
                float u0 = g_u0f[idx], u1 = g_u0f[idx+1];
                float h0 = u0*g_h0f[idx]   + (1.f-u0)*c0;
                float h1 = u1*g_h0f[idx+1] + (1.f-u1)*c1;
                g_h0f[idx] = h0; g_h0f[idx+1] = h1;
                sp2h(g_h0H, g_h0L, idx, h0, h1);
                int ci = r*1024 + c;
                sp2h(g_c1H, g_c1L, ci, h0, h1);
                sp2h(g_c2H[par], g_c2L[par], ci, h0, h1);
            });
    } else {
        if (w == 0) return;
        int par = (w - 1) & 1;
        mma_gemm_h3<64,32>(g_c2H[par], g_c2L[par], 1024, mt*64,
            g_WgruH + 5*SZGRU, 1024, n0, 1024,
            [&](int r, int c, float v0, float v1) {
                int idx = r*Hh + c;
                float c0 = tanhf(v0 + bc1[c]), c1 = tanhf(v1 + bc1[c+1]);
                float u0 = g_u1f[idx], u1 = g_u1f[idx+1];
                float h0 = u0*g_h1f[idx]   + (1.f-u0)*c0;
                float h1 = u1*g_h1f[idx+1] + (1.f-u1)*c1;
                g_h1f[idx] = h0; g_h1f[idx+1] = h1;
                sp2h(g_c1H, g_c1L, r*1024 + 512 + c, h0, h1);
                sp2h(g_X1ah, g_X1al, ((w-1)*Bb + r)*Hh + c, h0, h1);
            });
    }
}

// ---- logits: 2-term fp16 ----
__global__ __launch_bounds__(256, 2) void k_logits(const float* __restrict__ bout,
                                                   float* __restrict__ out)
{
    int n0 = blockIdx.x * 128, m0 = blockIdx.y * 128;
    mma_gemm_h2<128,128>(g_X1ah, g_X1al, Hh, m0, g_WoH, Hh, n0, Hh,
        [&](int r, int c, float v0, float v1) {
            if (c < Vv) {
                int t = r >> 7, b = r & 127;
                long long base = (long long)(b * Tt + t) * Vv;
                out[base + c] = v0 + bout[c];
                if (c + 1 < Vv) out[base + c + 1] = v1 + bout[c + 1];
            }
        });
}

__global__ __launch_bounds__(256) void k_final(float* __restrict__ out)
{
    int i = blockIdx.x * 256 + threadIdx.x;
    out[(long long)Bb * Tt * Vv + i] = (i >> 16) ? g_h1f[i & (BH-1)] : g_h0f[i & (BH-1)];
}

// ---- launch ----
extern "C" void kernel_launch(void* const* d_in, const int* in_sizes, int n_in,
                              void* d_out, int out_size)
{
    const float* vgg   = (const float*)d_in[0];
    const int*   xTok  = (const int*)  d_in[1];
    const float* emb   = (const float*)d_in[2];
    const float* W_in  = (const float*)d_in[3];
    const float* b_in  = (const float*)d_in[4];
    const float* Wu    = (const float*)d_in[5];
    const float* bu    = (const float*)d_in[6];
    const float* Wr    = (const float*)d_in[7];
    const float* br    = (const float*)d_in[8];
    const float* Wc    = (const float*)d_in[9];
    const float* bc    = (const float*)d_in[10];
    const float* W_out = (const float*)d_in[11];
    const float* b_out = (const float*)d_in[12];
    float* out = (float*)d_out;

    cudaFuncSetAttribute(k_xpre,   cudaFuncAttributeMaxDynamicSharedMemorySize, SMEM_H);
    cudaFuncSetAttribute(k_logits, cudaFuncAttributeMaxDynamicSharedMemorySize, SMEM_H);
    cudaFuncSetAttribute(k_ur,     cudaFuncAttributeMaxDynamicSharedMemorySize, S3H);
    cudaFuncSetAttribute(k_c,      cudaFuncAttributeMaxDynamicSharedMemorySize, S3H);

    bf16 *Wih, *Wil;
    cudaGetSymbolAddress((void**)&Wih, g_Win_h);
    cudaGetSymbolAddress((void**)&Wil, g_Win_l);

    pk_vgg<<<(Bb*Ff/2)/256, 256>>>(vgg);
    pk_T<<<dim3(16, 128), 256>>>(W_in, Wih, Wil, Ff, Hh);
    pk_gruH<<<dim3(16, 32, 6), 256>>>(Wu, Wr, Wc);
    pk_Wo<<<dim3(Vpad/32, 16), 256>>>(W_out);

    k_initp<<<128, 256, SMEM_S>>>();
    k_initf<<<(BH/2)/256, 256>>>(b_in);
    k_gather<<<(TBH/2)/256, 256>>>(emb, xTok);
    k_xpre<<<dim3(4, Tt*Bb/128, 3), 256, SMEM_H>>>(bu, br, bc);

    for (int w = 0; w <= Tt; w++) {
        k_ur<<<dim3(16, 2, 4), 256, S3H>>>(w, bu + Hh, br + Hh);
        k_c <<<dim3(16, 2, 2), 256, S3H>>>(w, bc + Hh);
    }

    k_logits<<<dim3(Vpad/128, Tt*Bb/128), 256, SMEM_H>>>(b_out, out);
    k_final<<<(2*BH)/256, 256>>>(out);
}

// round 14
// speedup vs baseline: 1.9461x; 1.3573x over previous
#include <cuda_runtime.h>
#include <cuda_bf16.h>
#include <cuda_fp16.h>
#include <math.h>
#include <stdint.h>

#define Bb 128
#define Tt 30
#define Vv 10000
#define Hh 512
#define Ff 4096
#define BH (Bb*Hh)
#define TBH (Tt*Bb*Hh)
#define Vpad 10112
#define SZGRU (512*1024)

typedef __nv_bfloat16 bf16;
typedef __nv_bfloat162 bf162;

__device__ float g_h0f[BH], g_h1f[BH], g_u0f[BH], g_u1f[BH];
__device__ float g_Xu0[TBH], g_Xr0[TBH], g_Xc0[TBH];
__device__ float g_ipart[4][BH];

// bf16 operands (init GEMM only)
__device__ __align__(16) bf16 g_vgg_h[Bb*Ff], g_vgg_l[Bb*Ff];
__device__ __align__(16) bf16 g_Win_h[Hh*Ff], g_Win_l[Hh*Ff];

// fp16 activations (single precision term)
__device__ __align__(16) __half g_xembH[TBH];
__device__ __align__(16) __half g_h0H[BH];
__device__ __align__(16) __half g_rh0H[BH];
__device__ __align__(16) __half g_c1H[Bb*1024];
__device__ __align__(16) __half g_c2H[2][Bb*1024];
__device__ __align__(16) __half g_X1ah[TBH];

// fp16 weights
__device__ __align__(16) __half g_WgruH[6*SZGRU];   // [z][N=512, K=1024]
__device__ __align__(16) __half g_WoH[Vpad*Hh];     // [N, K=512]

__device__ __forceinline__ uint32_t smem_u32(const void* p) {
    uint32_t a;
    asm("{ .reg .u64 t; cvta.to.shared.u64 t, %1; cvt.u32.u64 %0, t; }" : "=r"(a) : "l"(p));
    return a;
}
__device__ __forceinline__ void cpasync16(uint32_t dst, const void* src) {
    asm volatile("cp.async.cg.shared.global [%0], [%1], 16;" :: "r"(dst), "l"(src) : "memory");
}
#define CP_COMMIT() asm volatile("cp.async.commit_group;" ::: "memory")
#define CP_WAIT2()  asm volatile("cp.async.wait_group 2;" ::: "memory")
#define CP_WAIT1()  asm volatile("cp.async.wait_group 1;" ::: "memory")
#define CP_WAIT0()  asm volatile("cp.async.wait_group 0;" ::: "memory")
#define LDSM4(R, addr) \
    asm volatile("ldmatrix.sync.aligned.m8n8.x4.shared.b16 {%0,%1,%2,%3}, [%4];" \
        : "=r"((R)[0]), "=r"((R)[1]), "=r"((R)[2]), "=r"((R)[3]) : "r"(addr))

__device__ __forceinline__ void mmaop(float* c, const uint32_t* a, const uint32_t* b) {
    asm volatile("mma.sync.aligned.m16n8k16.row.col.f32.bf16.bf16.f32 "
        "{%0,%1,%2,%3}, {%4,%5,%6,%7}, {%8,%9}, {%0,%1,%2,%3};"
        : "+f"(c[0]), "+f"(c[1]), "+f"(c[2]), "+f"(c[3])
        : "r"(a[0]), "r"(a[1]), "r"(a[2]), "r"(a[3]), "r"(b[0]), "r"(b[1]));
}
__device__ __forceinline__ void mmaop_h(float* c, const uint32_t* a, const uint32_t* b) {
    asm volatile("mma.sync.aligned.m16n8k16.row.col.f32.f16.f16.f32 "
        "{%0,%1,%2,%3}, {%4,%5,%6,%7}, {%8,%9}, {%0,%1,%2,%3};"
        : "+f"(c[0]), "+f"(c[1]), "+f"(c[2]), "+f"(c[3])
        : "r"(a[0]), "r"(a[1]), "r"(a[2]), "r"(a[3]), "r"(b[0]), "r"(b[1]));
}
__device__ __forceinline__ float sigmoidf_(float x) { return 1.0f / (1.0f + expf(-x)); }
__device__ __forceinline__ void sp2(bf16* H, bf16* L, int i, float a, float b) {
    bf16 ha = __float2bfloat16(a), hb = __float2bfloat16(b);
    bf162 hv; hv.x = ha; hv.y = hb;
    bf162 lv; lv.x = __float2bfloat16(a - __bfloat162float(ha));
    lv.y = __float2bfloat16(b - __bfloat162float(hb));
    *(bf162*)&H[i] = hv; *(bf162*)&L[i] = lv;
}
__device__ __forceinline__ void sph(__half* H, int i, float a, float b) {
    __half2 hv; hv.x = __float2half_rn(a); hv.y = __float2half_rn(b);
    *(__half2*)&H[i] = hv;
}

// ---- split-3 bf16 mma GEMM (init only), 2-stage KT=32 ----
#define ROWB 80
template<int TM, int TN, typename Epi>
__device__ __forceinline__ void mma_gemm(
    const bf16* __restrict__ Ah, const bf16* __restrict__ Al, int lda, int m0,
    const bf16* __restrict__ Bh, const bf16* __restrict__ Bl, int ldb, int n0,
    int K, Epi epi)
{
    extern __shared__ char smem[];
    constexpr int ASZ = TM * ROWB, BSZ = TN * ROWB, STG = 2*ASZ + 2*BSZ;
    constexpr int WM = TM / 4, WN = TN / 2, FM = WM / 16, NF = WN / 8;
    constexpr int GG = (NF > 4) ? 4 : NF;
    const uint32_t s0 = smem_u32(smem);
    const int tid = threadIdx.x, lane = tid & 31, wid = tid >> 5;
    const int wm = wid >> 1, wn = wid & 1;
    const int lrow = lane & 15, lhalf = lane >> 4;
    float acc[FM][NF][4] = {};

    auto issue = [&](int ch, int st) {
        uint32_t d = s0 + st * STG;
        int k0 = ch * 32;
        #pragma unroll
        for (int v = tid; v < TM * 4; v += 256) {
            int row = v >> 2, c = v & 3;
            cpasync16(d + row*ROWB + c*16,       Ah + (m0+row)*lda + k0 + c*8);
            cpasync16(d + ASZ + row*ROWB + c*16, Al + (m0+row)*lda + k0 + c*8);
        }
        #pragma unroll
        for (int v = tid; v < TN * 4; v += 256) {
            int row = v >> 2, c = v & 3;
            cpasync16(d + 2*ASZ + row*ROWB + c*16,       Bh + (n0+row)*ldb + k0 + c*8);
            cpasync16(d + 2*ASZ + BSZ + row*ROWB + c*16, Bl + (n0+row)*ldb + k0 + c*8);
        }
        CP_COMMIT();
    };

    const int NC = K / 32;
    issue(0, 0);
    for (int ch = 0; ch < NC; ch++) {
        int st = ch & 1;
        if (ch + 1 < NC) { issue(ch + 1, (ch + 1) & 1); CP_WAIT1(); }
        else CP_WAIT0();
        __syncthreads();
        uint32_t d = s0 + st * STG;
        #pragma unroll
        for (int kk = 0; kk < 2; kk++) {
            uint32_t ah[FM][4], al[FM][4];
            #pragma unroll
            for (int f = 0; f < FM; f++) {
                uint32_t a = d + (wm*WM + f*16 + lrow)*ROWB + lhalf*16 + kk*32;
                LDSM4(ah[f], a);
                LDSM4(al[f], a + ASZ);
            }
            #pragma unroll
            for (int gg = 0; gg < NF; gg += GG) {
                uint32_t bh[GG][2], bl[GG][2];
                #pragma unroll
                for (int g2 = 0; g2 < GG; g2 += 2) {
                    int g = gg + g2;
                    uint32_t b = d + 2*ASZ + (wn*WN + g*8 + lrow)*ROWB + lhalf*16 + kk*32;
                    uint32_t t4[4];
                    LDSM4(t4, b);
                    bh[g2][0]=t4[0]; bh[g2][1]=t4[2]; bh[g2+1][0]=t4[1]; bh[g2+1][1]=t4[3];
                    LDSM4(t4, b + BSZ);
                    bl[g2][0]=t4[0]; bl[g2][1]=t4[2]; bl[g2+1][0]=t4[1]; bl[g2+1][1]=t4[3];
                }
                #pragma unroll
                for (int f = 0; f < FM; f++)
                    #pragma unroll
                    for (int g2 = 0; g2 < GG; g2++) {
                        mmaop(acc[f][gg+g2], ah[f], bh[g2]);
                        mmaop(acc[f][gg+g2], ah[f], bl[g2]);
                        mmaop(acc[f][gg+g2], al[f], bh[g2]);
                    }
            }
        }
        __syncthreads();
    }
    #pragma unroll
    for (int f = 0; f < FM; f++)
        #pragma unroll
        for (int g = 0; g < NF; g++) {
            int r = m0 + wm*WM + f*16 + (lane >> 2);
            int c = n0 + wn*WN + g*8 + (lane & 3)*2;
            epi(r,     c, acc[f][g][0], acc[f][g][1]);
            epi(r + 8, c, acc[f][g][2], acc[f][g][3]);
        }
}

// ---- 1-term fp16 GEMM, 2-stage KT=32 (xpre / logits) ----
template<int TM, int TN, typename Epi>
__device__ __forceinline__ void gemm1_2s(
    const __half* __restrict__ A, int lda, int m0,
    const __half* __restrict__ B, int ldb, int n0, int K, Epi epi)
{
    extern __shared__ char smem[];
    constexpr int ASZ = TM * ROWB, BSZ = TN * ROWB, STG = ASZ + BSZ;
    constexpr int WM = TM / 4, WN = TN / 2, FM = WM / 16, NF = WN / 8;
    constexpr int GG = (NF > 4) ? 4 : NF;
    const uint32_t s0 = smem_u32(smem);
    const int tid = threadIdx.x, lane = tid & 31, wid = tid >> 5;
    const int wm = wid >> 1, wn = wid & 1;
    const int lrow = lane & 15, lhalf = lane >> 4;
    float acc[FM][NF][4] = {};

    auto issue = [&](int ch, int st) {
        uint32_t d = s0 + st * STG;
        int k0 = ch * 32;
        #pragma unroll
        for (int v = tid; v < TM * 4; v += 256) {
            int row = v >> 2, c = v & 3;
            cpasync16(d + row*ROWB + c*16, A + (m0+row)*lda + k0 + c*8);
        }
        #pragma unroll
        for (int v = tid; v < TN * 4; v += 256) {
            int row = v >> 2, c = v & 3;
            cpasync16(d + ASZ + row*ROWB + c*16, B + (n0+row)*ldb + k0 + c*8);
        }
        CP_COMMIT();
    };

    const int NC = K / 32;
    issue(0, 0);
    for (int ch = 0; ch < NC; ch++) {
        int st = ch & 1;
        if (ch + 1 < NC) { issue(ch + 1, (ch + 1) & 1); CP_WAIT1(); }
        else CP_WAIT0();
        __syncthreads();
        uint32_t d = s0 + st * STG;
        #pragma unroll
        for (int kk = 0; kk < 2; kk++) {
            uint32_t ah[FM][4];
            #pragma unroll
            for (int f = 0; f < FM; f++) {
                uint32_t a = d + (wm*WM + f*16 + lrow)*ROWB + lhalf*16 + kk*32;
                LDSM4(ah[f], a);
            }
            #pragma unroll
            for (int gg = 0; gg < NF; gg += GG) {
                uint32_t bh[GG][2];
                #pragma unroll
                for (int g2 = 0; g2 < GG; g2 += 2) {
                    int g = gg + g2;
                    uint32_t b = d + ASZ + (wn*WN + g*8 + lrow)*ROWB + lhalf*16 + kk*32;
                    uint32_t t4[4];
                    LDSM4(t4, b);
                    bh[g2][0]=t4[0]; bh[g2][1]=t4[2]; bh[g2+1][0]=t4[1]; bh[g2+1][1]=t4[3];
                }
                #pragma unroll
                for (int f = 0; f < FM; f++)
                    #pragma unroll
                    for (int g2 = 0; g2 < GG; g2++)
                        mmaop_h(acc[f][gg+g2], ah[f], bh[g2]);
            }
        }
        __syncthreads();
    }
    #pragma unroll
    for (int f = 0; f < FM; f++)
        #pragma unroll
        for (int g = 0; g < NF; g++) {
            int r = m0 + wm*WM + f*16 + (lane >> 2);
            int c = n0 + wn*WN + g*8 + (lane & 3)*2;
            epi(r,     c, acc[f][g][0], acc[f][g][1]);
            epi(r + 8, c, acc[f][g][2], acc[f][g][3]);
        }
}

// ---- 1-term fp16 GEMM, 3-stage KT=64 (scan) ----
#define ROWC 144
template<int TM, int TN, typename Epi>
__device__ __forceinline__ void gemm1_3s(
    const __half* __restrict__ A, int lda, int m0,
    const __half* __restrict__ B, int ldb, int n0, int K, Epi epi)
{
    extern __shared__ char smem[];
    constexpr int ASZ = TM * ROWC, BSZ = TN * ROWC, STG = ASZ + BSZ;
    constexpr int WM = TM / 4, WN = TN / 2, FM = WM / 16, NF = WN / 8;
    const uint32_t s0 = smem_u32(smem);
    const int tid = threadIdx.x, lane = tid & 31, wid = tid >> 5;
    const int wm = wid >> 1, wn = wid & 1;
    const int lrow = lane & 15, lhalf = lane >> 4;
    float acc[FM][NF][4] = {};

    auto issue = [&](int ch, int st) {
        uint32_t d = s0 + st * STG;
        int k0 = ch * 64;
        #pragma unroll
        for (int v = tid; v < TM * 8; v += 256) {
            int row = v >> 3, c = v & 7;
            cpasync16(d + row*ROWC + c*16, A + (m0+row)*lda + k0 + c*8);
        }
        #pragma unroll
        for (int v = tid; v < TN * 8; v += 256) {
            int row = v >> 3, c = v & 7;
            cpasync16(d + ASZ + row*ROWC + c*16, B + (n0+row)*ldb + k0 + c*8);
        }
        CP_COMMIT();
    };

    const int NC = K / 64;
    issue(0, 0);
    issue(1, 1);
    for (int ch = 0; ch < NC; ch++) {
        if (ch + 2 < NC) { issue(ch + 2, (ch + 2) % 3); CP_WAIT2(); }
        else if (ch + 1 < NC) CP_WAIT1();
        else CP_WAIT0();
        __syncthreads();
        uint32_t d = s0 + (ch % 3) * STG;
        #pragma unroll
        for (int kk = 0; kk < 4; kk++) {
            uint32_t ah[FM][4], bh[NF][2];
            #pragma unroll
            for (int f = 0; f < FM; f++) {
                uint32_t a = d + (wm*WM + f*16 + lrow)*ROWC + lhalf*16 + kk*32;
                LDSM4(ah[f], a);
            }
            #pragma unroll
            for (int g = 0; g < NF; g += 2) {
                uint32_t b = d + ASZ + (wn*WN + g*8 + lrow)*ROWC + lhalf*16 + kk*32;
                uint32_t t4[4];
                LDSM4(t4, b);
                bh[g][0]=t4[0]; bh[g][1]=t4[2]; bh[g+1][0]=t4[1]; bh[g+1][1]=t4[3];
            }
            #pragma unroll
            for (int f = 0; f < FM; f++)
                #pragma unroll
                for (int g = 0; g < NF; g++)
                    mmaop_h(acc[f][g], ah[f], bh[g]);
        }
        __syncthreads();
    }
    #pragma unroll
    for (int f = 0; f < FM; f++)
        #pragma unroll
        for (int g = 0; g < NF; g++) {
            int r = m0 + wm*WM + f*16 + (lane >> 2);
            int c = n0 + wn*WN + g*8 + (lane & 3)*2;
            epi(r,     c, acc[f][g][0], acc[f][g][1]);
            epi(r + 8, c, acc[f][g][2], acc[f][g][3]);
        }
}
#define SMEM_S  (2 * (2*64*ROWB + 2*32*ROWB))      // 30720 (init 3-term)
#define S1_3    (3 * (64*ROWC + 32*ROWC))          // 41472 (scan 1-term 3-stage)
#define S1_2    (2 * (128*ROWB + 128*ROWB))        // 40960 (xpre/logits 1-term)

// ---- prepack ----
__global__ __launch_bounds__(256) void pk_T(const float* __restrict__ src,
                                            bf16* __restrict__ dh, bf16* __restrict__ dl,
                                            int K, int N)
{
    __shared__ float tile[32][33];
    int kb = blockIdx.y * 32, nb = blockIdx.x * 32;
    int tx = threadIdx.x & 31, ty = threadIdx.x >> 5;
    for (int i = ty; i < 32; i += 8)
        tile[i][tx] = src[(kb + i) * N + nb + tx];
    __syncthreads();
    for (int i = ty; i < 32; i += 8) {
        int n = nb + i, k = kb + tx;
        float x = tile[tx][i];
        bf16 h = __float2bfloat16(x);
        dh[n * K + k] = h;
        dl[n * K + k] = __float2bfloat16(x - __bfloat162float(h));
    }
}
__global__ __launch_bounds__(256) void pk_gruH(const float* __restrict__ Wu,
                                               const float* __restrict__ Wr,
                                               const float* __restrict__ Wc)
{
    __shared__ float tile[32][33];
    int z = blockIdx.z;
    int gate = (z < 3) ? z : z - 3, layer = z / 3;
    const float* src = ((gate == 0) ? Wu : (gate == 1) ? Wr : Wc) + layer * 1024 * Hh;
    int kb = blockIdx.y * 32, nb = blockIdx.x * 32;
    int tx = threadIdx.x & 31, ty = threadIdx.x >> 5;
    for (int i = ty; i < 32; i += 8)
        tile[i][tx] = src[(kb + i) * Hh + nb + tx];
    __syncthreads();
    for (int i = ty; i < 32; i += 8)
        g_WgruH[z*SZGRU + (nb + i) * 1024 + kb + tx] = __float2half_rn(tile[tx][i]);
}
__global__ __launch_bounds__(256) void pk_Wo(const float* __restrict__ src)
{
    __shared__ float tile[32][33];
    int kb = blockIdx.y * 32, nb = blockIdx.x * 32;
    int tx = threadIdx.x & 31, ty = threadIdx.x >> 5;
    for (int i = ty; i < 32; i += 8) {
        int n = nb + tx;
        tile[i][tx] = (n < Vv) ? src[(kb + i) * Vv + n] : 0.f;
    }
    __syncthreads();
    for (int i = ty; i < 32; i += 8)
        g_WoH[(nb + i) * Hh + kb + tx] = __float2half_rn(tile[tx][i]);
}
__global__ __launch_bounds__(256) void pk_vgg(const float* __restrict__ src)
{
    int i = (blockIdx.x * 256 + threadIdx.x) * 2;
    sp2(g_vgg_h, g_vgg_l, i, src[i], src[i + 1]);
}
__global__ __launch_bounds__(256) void k_gather(const float* __restrict__ emb,
                                                const int* __restrict__ tok)
{
    int idx = (blockIdx.x * 256 + threadIdx.x) * 2;
    int r = idx >> 9, e = idx & 511;
    int token = tok[(r & 127) * Tt + (r >> 7)];
    sph(g_xembH, idx, emb[token * Hh + e], emb[token * Hh + e + 1]);
}

// ---- init: split-K partials then finalize ----
__global__ __launch_bounds__(256, 1) void k_initp()
{
    int cta = blockIdx.x;
    int ks = cta >> 5, mt = (cta >> 4) & 1, nt = cta & 15;
    int koff = ks * 1024;
    float* out = g_ipart[ks];
    mma_gemm<64,32>(g_vgg_h + koff, g_vgg_l + koff, Ff, mt*64,
                    g_Win_h + koff, g_Win_l + koff, Ff, nt*32, 1024,
        [&](int r, int c, float v0, float v1) {
            out[r*Hh + c] = v0; out[r*Hh + c + 1] = v1;
        });
}
__global__ __launch_bounds__(256) void k_initf(const float* __restrict__ b_in)
{
    int i = (blockIdx.x * 256 + threadIdx.x) * 2;
    float v0 = tanhf(g_ipart[0][i] + g_ipart[1][i] + g_ipart[2][i] + g_ipart[3][i]
                     + b_in[i & 511]);
    float v1 = tanhf(g_ipart[0][i+1] + g_ipart[1][i+1] + g_ipart[2][i+1] + g_ipart[3][i+1]
                     + b_in[(i+1) & 511]);
    g_h0f[i] = v0; g_h0f[i+1] = v1;
    g_h1f[i] = v0; g_h1f[i+1] = v1;
    sph(g_h0H, i, v0, v1);
    int ci = (i >> 9) * 1024 + 512 + (i & 511);
    sph(g_c1H, ci, v0, v1);
}

// ---- layer0 x-projections for all t (128x128, 1-term fp16) ----
__global__ __launch_bounds__(256, 2) void k_xpre(const float* __restrict__ bu,
                                                 const float* __restrict__ br,
                                                 const float* __restrict__ bc)
{
    int n0 = blockIdx.x * 128, m0 = blockIdx.y * 128, gate = blockIdx.z;
    const float* bi = (gate == 0) ? bu : (gate == 1) ? br : bc;
    float* out = (gate == 0) ? g_Xu0 : (gate == 1) ? g_Xr0 : g_Xc0;
    gemm1_2s<128,128>(g_xembH, Hh, m0, g_WgruH + gate*SZGRU, 1024, n0, Hh,
        [&](int r, int c, float v0, float v1) {
            float2 val = make_float2(v0 + bi[c], v1 + bi[c + 1]);
            *(float2*)&out[r*Hh + c] = val;
        });
}

// ---- wave UR: z={0,1}: layer0 u/r @t=w ; z={2,3}: layer1 u/r @t=w-1 ----
__global__ __launch_bounds__(256, 1) void k_ur(int w,
                                               const float* __restrict__ bu1,
                                               const float* __restrict__ br1)
{
    int nt = blockIdx.x, mt = blockIdx.y, z = blockIdx.z;
    int n0 = nt * 32;
    if (z < 2) {
        if (w >= Tt) return;
        int gate = z;
        const float* X = (gate ? g_Xr0 : g_Xu0) + w * BH;
        gemm1_3s<64,32>(g_h0H, Hh, mt*64,
            g_WgruH + gate*SZGRU + 512, 1024, n0, Hh,
            [&](int r, int c, float v0, float v1) {
                int idx = r*Hh + c;
                float s0 = sigmoidf_(v0 + X[idx]);
                float s1 = sigmoidf_(v1 + X[idx+1]);
                if (gate == 0) { g_u0f[idx] = s0; g_u0f[idx+1] = s1; }
                else sph(g_rh0H, idx, s0*g_h0f[idx], s1*g_h0f[idx+1]);
            });
    } else {
        if (w == 0) return;
        int gate = z - 2, par = (w - 1) & 1;
        const float* bi = gate ? br1 : bu1;
        gemm1_3s<64,32>(g_c1H, 1024, mt*64,
            g_WgruH + (3+gate)*SZGRU, 1024, n0, 1024,
            [&](int r, int c, float v0, float v1) {
                int idx = r*Hh + c;
                float s0 = sigmoidf_(v0 + bi[c]);
                float s1 = sigmoidf_(v1 + bi[c+1]);
                if (gate == 0) { g_u1f[idx] = s0; g_u1f[idx+1] = s1; }
                else sph(g_c2H[par], r*1024 + 512 + c,
                         s0*g_h1f[idx], s1*g_h1f[idx+1]);
            });
    }
}

// ---- wave C: z=0: layer0 cand+update @t=w ; z=1: layer1 @t=w-1 ----
__global__ __launch_bounds__(256, 1) void k_c(int w, const float* __restrict__ bc1)
{
    int nt = blockIdx.x, mt = blockIdx.y, z = blockIdx.z;
    int n0 = nt * 32;
    if (z == 0) {
        if (w >= Tt) return;
        int par = w & 1;
        const float* Xc = g_Xc0 + w * BH;
        gemm1_3s<64,32>(g_rh0H, Hh, mt*64,
            g_WgruH + 2*SZGRU + 512, 1024, n0, Hh,
            [&](int r, int c, float v0, float v1) {
                int idx = r*Hh + c;
                float c0 = tanhf(v0 + Xc[idx]), c1 = tanhf(v1 + Xc[idx+1]);
                float u0 = g_u0f[idx], u1 = g_u0f[idx+1];
                float h0 = u0*g_h0f[idx]   + (1.f-u0)*c0;
                float h1 = u1*g_h0f[idx+1] + (1.f-u1)*c1;
                g_h0f[idx] = h0; g_h0f[idx+1] = h1;
                sph(g_h0H, idx, h0, h1);
                int ci = r*1024 + c;
                sph(g_c1H, ci, h0, h1);
                sph(g_c2H[par], ci, h0, h1);
            });
    } else {
        if (w == 0) return;
        int par = (w - 1) & 1;
        gemm1_3s<64,32>(g_c2H[par], 1024, mt*64,
            g_WgruH + 5*SZGRU, 1024, n0, 1024,
            [&](int r, int c, float v0, float v1) {
                int idx = r*Hh + c;
                float c0 = tanhf(v0 + bc1[c]), c1 = tanhf(v1 + bc1[c+1]);
                float u0 = g_u1f[idx], u1 = g_u1f[idx+1];
                float h0 = u0*g_h1f[idx]   + (1.f-u0)*c0;
                float h1 = u1*g_h1f[idx+1] + (1.f-u1)*c1;
                g_h1f[idx] = h0; g_h1f[idx+1] = h1;
                sph(g_c1H, r*1024 + 512 + c, h0, h1);
                sph(g_X1ah, ((w-1)*Bb + r)*Hh + c, h0, h1);
            });
    }
}

// ---- logits: 1-term fp16 ----
__global__ __launch_bounds__(256, 2) void k_logits(const float* __restrict__ bout,
                                                   float* __restrict__ out)
{
    int n0 = blockIdx.x * 128, m0 = blockIdx.y * 128;
    gemm1_2s<128,128>(g_X1ah, Hh, m0, g_WoH, Hh, n0, Hh,
        [&](int r, int c, float v0, float v1) {
            if (c < Vv) {
                int t = r >> 7, b = r & 127;
                long long base = (long long)(b * Tt + t) * Vv;
                out[base + c] = v0 + bout[c];
                if (c + 1 < Vv) out[base + c + 1] = v1 + bout[c + 1];
            }
        });
}

__global__ __launch_bounds__(256) void k_final(float* __restrict__ out)
{
    int i = blockIdx.x * 256 + threadIdx.x;
    out[(long long)Bb * Tt * Vv + i] = (i >> 16) ? g_h1f[i & (BH-1)] : g_h0f[i & (BH-1)];
}

// ---- launch ----
extern "C" void kernel_launch(void* const* d_in, const int* in_sizes, int n_in,
                              void* d_out, int out_size)
{
    const float* vgg   = (const float*)d_in[0];
    const int*   xTok  = (const int*)  d_in[1];
    const float* emb   = (const float*)d_in[2];
    const float* W_in  = (const float*)d_in[3];
    const float* b_in  = (const float*)d_in[4];
    const float* Wu    = (const float*)d_in[5];
    const float* bu    = (const float*)d_in[6];
    const float* Wr    = (const float*)d_in[7];
    const float* br    = (const float*)d_in[8];
    const float* Wc    = (const float*)d_in[9];
    const float* bc    = (const float*)d_in[10];
    const float* W_out = (const float*)d_in[11];
    const float* b_out = (const float*)d_in[12];
    float* out = (float*)d_out;

    cudaFuncSetAttribute(k_xpre,   cudaFuncAttributeMaxDynamicSharedMemorySize, S1_2);
    cudaFuncSetAttribute(k_logits, cudaFuncAttributeMaxDynamicSharedMemorySize, S1_2);
    cudaFuncSetAttribute(k_ur,     cudaFuncAttributeMaxDynamicSharedMemorySize, S1_3);
    cudaFuncSetAttribute(k_c,      cudaFuncAttributeMaxDynamicSharedMemorySize, S1_3);

    bf16 *Wih, *Wil;
    cudaGetSymbolAddress((void**)&Wih, g_Win_h);
    cudaGetSymbolAddress((void**)&Wil, g_Win_l);

    pk_vgg<<<(Bb*Ff/2)/256, 256>>>(vgg);
    pk_T<<<dim3(16, 128), 256>>>(W_in, Wih, Wil, Ff, Hh);
    pk_gruH<<<dim3(16, 32, 6), 256>>>(Wu, Wr, Wc);
    pk_Wo<<<dim3(Vpad/32, 16), 256>>>(W_out);

    k_initp<<<128, 256, SMEM_S>>>();
    k_initf<<<(BH/2)/256, 256>>>(b_in);
    k_gather<<<(TBH/2)/256, 256>>>(emb, xTok);
    k_xpre<<<dim3(4, Tt*Bb/128, 3), 256, S1_2>>>(bu, br, bc);

    for (int w = 0; w <= Tt; w++) {
        k_ur<<<dim3(16, 2, 4), 256, S1_3>>>(w, bu + Hh, br + Hh);
        k_c <<<dim3(16, 2, 2), 256, S1_3>>>(w, bc + Hh);
    }

    k_logits<<<dim3(Vpad/128, Tt*Bb/128), 256, S1_2>>>(b_out, out);
    k_final<<<(2*BH)/256, 256>>>(out);
}